// round 13
// baseline (speedup 1.0000x reference)
#include <cuda_runtime.h>
#include <cstdint>

// ---------------- problem constants ----------------
#define B_     4096
#define OBS_   64
#define EP_    10
#define IN_    640      // OBS*EP
#define H_     1024
#define AD_    16
#define DP_    10
#define OUT_   160      // AD*DP
#define T_     8
#define M_     (B_ * T_)   // 32768 batched rows, ordered m = b*8 + t

#define CDECAY 0.5f
#define VTH    0.5f
#define THV   (-0.172f)
#define THU    0.529f
#define THR    0.021f
#define THS    0.132f

// ---------------- device scratch ----------------
__device__ __align__(128) int8_t g_spikes[(size_t)M_ * (size_t)IN_];   // 21 MB, [b*8+t][i]
__device__ __align__(128) int8_t g_sa[(size_t)M_ * (size_t)H_];        // 33.5 MB
__device__ __align__(128) int8_t g_sb[(size_t)M_ * (size_t)H_];        // 33.5 MB
__device__ __align__(128) float g_x3[(size_t)M_ * (size_t)OUT_];       // 21 MB
__device__ __align__(128) float g_w1t[(size_t)IN_ * (size_t)H_];   // [640][1024]
__device__ __align__(128) float g_w2t[(size_t)H_ * (size_t)H_];    // [1024][1024]
__device__ __align__(128) float g_wot[(size_t)H_ * 256];           // [1024][256], cols>=160 zero

// ---------------- helpers ----------------
__device__ __forceinline__ uint32_t smem_u32(const void* p) {
    uint32_t a;
    asm("{ .reg .u64 t; cvta.to.shared.u64 t, %1; cvt.u32.u64 %0, t; }" : "=r"(a) : "l"(p));
    return a;
}
__device__ __forceinline__ void cp_async16(uint32_t saddr, const void* g) {
    asm volatile("cp.async.cg.shared.global [%0], [%1], 16;" :: "r"(saddr), "l"(g));
}
#define CP_COMMIT() asm volatile("cp.async.commit_group;" ::: "memory")
#define CP_WAIT0()  asm volatile("cp.async.wait_group 0;" ::: "memory")
#define CP_WAIT1()  asm volatile("cp.async.wait_group 1;" ::: "memory")

__device__ __forceinline__ void lds_v2u64(unsigned long long& a, unsigned long long& b, uint32_t addr) {
    asm volatile("ld.shared.v2.u64 {%0,%1}, [%2];" : "=l"(a), "=l"(b) : "r"(addr));
}
__device__ __forceinline__ void sts64(uint32_t addr, unsigned long long d) {
    asm volatile("st.shared.b64 [%0], %1;" :: "r"(addr), "l"(d));
}
__device__ __forceinline__ unsigned long long dupbit(uint32_t word, int b) {
    uint32_t f = ((word >> (8 * b)) & 1u) * 0x3f800000u;
    unsigned long long d;
    asm("mov.b64 %0, {%1,%1};" : "=l"(d) : "r"(f));
    return d;
}
// packed fp32 pair FMA: per-lane IEEE RN fp32 fma (bitwise == scalar FFMA chain)
__device__ __forceinline__ void fma2(unsigned long long& d, unsigned long long a, unsigned long long b) {
    asm("fma.rn.f32x2 %0, %1, %2, %0;" : "+l"(d) : "l"(a), "l"(b));
}
__device__ __forceinline__ float f2lo(unsigned long long u) {
    return __int_as_float((int)(unsigned)(u & 0xffffffffull));
}
__device__ __forceinline__ float f2hi(unsigned long long u) {
    return __int_as_float((int)(unsigned)(u >> 32));
}

// ---------------- batched f32x2 GEMM, sequential-k fp32 semantics ----------------
// X[m][n] = sum_{k ascending} A[m][k]*W[n][k], fp32 RN FMA chain per output.
// A: s8 spikes [M][KBASE], m = b*8+t. WT: fp32 [KBASE][WLD] k-major.
// CTA 128x128, BK=32, 256 threads; thread: 8 rows (= t 0..7 of one b) x 8 cols.
// Smem (64KB total): A DUPLICATED f32x2 SINGLE-buffered [32][128] f64 (32KB);
//                    W plain DOUBLE-buffered [2][32][128] f32 (32KB) via cp.async.
// Inner k: 4 LDS(A, broadcast) + 2 LDS(W) + 32 fma2 = 38 issue slots.
// MODE 0: plain store to X. MODE 1: fused hidden-neuron scan over t, write s8 spikes.
template<int KBASE, int MODE>
__global__ __launch_bounds__(256, 2) void gemm_f2(
    const int8_t* __restrict__ A, const float* __restrict__ WT,
    const float* __restrict__ bias,
    float* __restrict__ X, int8_t* __restrict__ S,
    int WLD, int XLD, int NTOT) {

    constexpr int KT = KBASE / 32;
    constexpr uint32_t ABUF = 32 * 128 * 8;   // dup f64, single buffer
    constexpr uint32_t WBUF = 32 * 128 * 4;

    extern __shared__ char smraw[];
    const uint32_t ab0 = smem_u32(smraw);
    const uint32_t wb0 = ab0 + ABUF;

    const int tid  = threadIdx.x;
    const int trow = tid >> 4;     // 0..15
    const int tcol = tid & 15;     // 0..15
    const int bm0 = blockIdx.y * 128;
    const int bn0 = blockIdx.x * 128;

    const int arowi = tid & 127;
    const int khalf = tid >> 7;    // 0/1
    const int8_t* arow = A + (size_t)(bm0 + arowi) * KBASE + khalf * 16;

    uint4 arg;
    auto ldgA = [&](int t) { arg = *(const uint4*)(arow + t * 32); };
    auto cpW = [&](int t) {
        const float* src = WT + (size_t)(t * 32) * WLD + bn0;
        const uint32_t dst = wb0 + (uint32_t)(t & 1) * WBUF;
#pragma unroll
        for (int q = 0; q < 4; q++) {
            int ch = tid + q * 256;           // 0..1023
            int row = ch >> 5, c16 = ch & 31; // 32 rows x 32 16B-chunks
            cp_async16(dst + (uint32_t)(row * 128 + c16 * 4) * 4,
                       src + (size_t)row * WLD + c16 * 4);
        }
        CP_COMMIT();
    };
    auto stsA = [&]() {
        // k = khalf*16 + w*4 + b; addr = (k*128 + arowi)*8, duplicated f32x2
        uint32_t base = ab0 + (uint32_t)(khalf * 16 * 128 + arowi) * 8u;
#pragma unroll
        for (int w = 0; w < 4; w++) {
            uint32_t x = ((const uint32_t*)&arg)[w];
#pragma unroll
            for (int b = 0; b < 4; b++)
                sts64(base + (uint32_t)((w * 4 + b) * 128) * 8u, dupbit(x, b));
        }
    };

    unsigned long long acc[8][4];
#pragma unroll
    for (int i = 0; i < 8; i++)
#pragma unroll
        for (int j = 0; j < 4; j++) acc[i][j] = 0ull;

    // prologue: A tile 0 expanded; W0, W1 in flight; A tile 1 in regs
    ldgA(0); cpW(0); stsA();
    if (KT > 1) { ldgA(1); cpW(1); }

    for (int i = 0; i < KT; i++) {
        if (i + 1 < KT) CP_WAIT1(); else CP_WAIT0();
        __syncthreads();   // W_i visible to all; stsA for tile i complete

        const uint32_t ab = ab0 + (uint32_t)(trow * 8) * 8u;
        const uint32_t wb = wb0 + (uint32_t)(i & 1) * WBUF + (uint32_t)(tcol * 8) * 4u;
#pragma unroll
        for (int k = 0; k < 32; k++) {
            unsigned long long aa[8], ww[4];
            const uint32_t ak = ab + (uint32_t)(k * 128) * 8u;
            lds_v2u64(aa[0], aa[1], ak);
            lds_v2u64(aa[2], aa[3], ak + 16u);
            lds_v2u64(aa[4], aa[5], ak + 32u);
            lds_v2u64(aa[6], aa[7], ak + 48u);
            const uint32_t wk = wb + (uint32_t)(k * 128) * 4u;
            lds_v2u64(ww[0], ww[1], wk);
            lds_v2u64(ww[2], ww[3], wk + 16u);
#pragma unroll
            for (int ii = 0; ii < 8; ii++)
#pragma unroll
                for (int jj = 0; jj < 4; jj++) fma2(acc[ii][jj], aa[ii], ww[jj]);
        }

        if (i + 1 < KT) {
            __syncthreads();   // all warps done reading A tile i
            stsA();            // expand A tile i+1 (regs from ldgA(i+1))
            if (i + 2 < KT) { ldgA(i + 2); cpW(i + 2); }
        }
    }

    if (MODE == 1) {
        // fused hidden-neuron scan over t (thread rows = t 0..7 of batch b)
        float bj[8];
#pragma unroll
        for (int cc = 0; cc < 8; cc++) bj[cc] = bias[bn0 + tcol * 8 + cc];
        unsigned long long srow[8];
#pragma unroll
        for (int i = 0; i < 8; i++) srow[i] = 0ull;
#pragma unroll
        for (int j = 0; j < 4; j++) {
#pragma unroll
            for (int e = 0; e < 2; e++) {
                const int cc = 2 * j + e;
                float c = 0.0f, vv = 0.0f, rr = 0.0f, ss = 0.0f;
#pragma unroll
                for (int i = 0; i < 8; i++) {
                    float xv = e ? f2hi(acc[i][j]) : f2lo(acc[i][j]);
                    c  = c * CDECAY + xv + bj[cc];
                    vv = vv * (1.0f - ss) + ss * THR;
                    rr = rr + ss * THS;
                    float vd = vv * vv - vv - rr + c;
                    float rd = THV * vv - THU * rr;
                    vv += vd; rr += rd;
                    ss = vv > VTH ? 1.0f : 0.0f;
                    srow[i] |= (unsigned long long)(ss != 0.0f ? 1u : 0u) << (8 * cc);
                }
            }
        }
#pragma unroll
        for (int i = 0; i < 8; i++) {
            size_t row = (size_t)(bm0 + trow * 8 + i);
            *(unsigned long long*)&S[row * H_ + bn0 + tcol * 8] = srow[i];
        }
    } else {
#pragma unroll
        for (int i = 0; i < 8; i++) {
            int row = bm0 + trow * 8 + i;
#pragma unroll
            for (int j = 0; j < 4; j++) {
                int col = bn0 + tcol * 8 + 2 * j;
                if (col < NTOT) {
                    *(float2*)&X[(size_t)row * XLD + col] =
                        make_float2(f2lo(acc[i][j]), f2hi(acc[i][j]));
                }
            }
        }
    }
}

// ---------------- weight transpose: w[N][K] -> wt[K][NP], zero-pad n>=N ----------------
__global__ void transpose_w(const float* __restrict__ w, float* __restrict__ wt,
                            int N, int K, int NP) {
    __shared__ float t[32][33];
    int tx = threadIdx.x, ty = threadIdx.y;  // 32 x 8
    int bx = blockIdx.x, by = blockIdx.y;
#pragma unroll
    for (int j = 0; j < 4; j++) {
        int n = bx * 32 + ty + j * 8;
        int k = by * 32 + tx;
        t[ty + j * 8][tx] = (n < N) ? w[(size_t)n * K + k] : 0.0f;
    }
    __syncthreads();
#pragma unroll
    for (int j = 0; j < 4; j++) {
        int k = by * 32 + ty + j * 8;
        int n = bx * 32 + tx;
        wt[(size_t)k * NP + n] = t[tx][ty + j * 8];
    }
}

// ---------------- encoder (writes spikes in m = b*8+t order) ----------------
__global__ void encoder_kernel(const float* __restrict__ obs,
                               const float* __restrict__ mean,
                               const float* __restrict__ stdv) {
    int idx = blockIdx.x * blockDim.x + threadIdx.x;
    if (idx >= B_ * IN_) return;
    int b = idx / IN_;
    int i = idx - b * IN_;
    int o = i / EP_;
    float d  = obs[b * OBS_ + o] - mean[i];
    float sd = stdv[i];
    float a  = expf(-0.5f * d * d / (sd * sd));
    float volt = 0.0f;
    int8_t* sp = g_spikes + (size_t)b * T_ * IN_ + i;
#pragma unroll
    for (int t = 0; t < T_; t++) {
        volt += a;
        float s = volt > 1.0f ? 1.0f : 0.0f;
        volt -= s;
        sp[(size_t)t * IN_] = (int8_t)s;
    }
}

// ---------------- output-layer scan: lateral conv + neuron + fr + decode ----------------
__global__ __launch_bounds__(256) void scan_out(
    const float* __restrict__ x3, const float* __restrict__ b_out,
    const float* __restrict__ conn_w, const float* __restrict__ conn_b,
    const float* __restrict__ dec_w, const float* __restrict__ dec_b,
    float* __restrict__ out) {
    __shared__ float cw[AD_ * DP_ * DP_];   // 1600
    for (int i = threadIdx.x; i < AD_ * DP_ * DP_; i += blockDim.x) cw[i] = conn_w[i];
    __syncthreads();

    int idx = blockIdx.x * blockDim.x + threadIdx.x;   // (b, a)
    if (idx >= B_ * AD_) return;
    int b = idx >> 4;
    int a = idx & 15;

    float cb[DP_], bo[DP_];
#pragma unroll
    for (int j = 0; j < DP_; j++) {
        cb[j] = conn_b[a * DP_ + j];
        bo[j] = b_out[a * DP_ + j];
    }
    const float* cwa = cw + a * DP_ * DP_;

    float cur[DP_], vv[DP_], rr[DP_], sp[DP_], fr[DP_];
#pragma unroll
    for (int j = 0; j < DP_; j++) { cur[j] = 0.f; vv[j] = 0.f; rr[j] = 0.f; sp[j] = 0.f; fr[j] = 0.f; }

    for (int t = 0; t < T_; t++) {
        const float* xp = x3 + ((size_t)b * T_ + t) * OUT_ + a * DP_;
        float sn[DP_];
#pragma unroll
        for (int j = 0; j < DP_; j++) {
            float lat = cb[j];
#pragma unroll
            for (int k = 0; k < DP_; k++) lat += sp[k] * cwa[j * DP_ + k];
            float c  = cur[j] * CDECAY + xp[j] + bo[j] + lat;
            float v2 = vv[j] * (1.0f - sp[j]) + sp[j] * THR;
            float r2 = rr[j] + sp[j] * THS;
            float vd = v2 * v2 - v2 - r2 + c;
            float rd = THV * v2 - THU * r2;
            v2 += vd; r2 += rd;
            sn[j] = v2 > VTH ? 1.0f : 0.0f;
            cur[j] = c; vv[j] = v2; rr[j] = r2;
        }
#pragma unroll
        for (int j = 0; j < DP_; j++) { sp[j] = sn[j]; fr[j] += sn[j]; }
    }

    float raw = dec_b[a];
#pragma unroll
    for (int p = 0; p < DP_; p++) raw += (fr[p] * 0.125f) * dec_w[a * DP_ + p];
    out[idx] = tanhf(raw);
}

// ---------------- launch ----------------
extern "C" void kernel_launch(void* const* d_in, const int* in_sizes, int n_in,
                              void* d_out, int out_size) {
    const float* obs    = (const float*)d_in[0];
    const float* mean   = (const float*)d_in[1];
    const float* stdv   = (const float*)d_in[2];
    const float* w1     = (const float*)d_in[3];
    const float* b1     = (const float*)d_in[4];
    const float* w2     = (const float*)d_in[5];
    const float* b2     = (const float*)d_in[6];
    const float* w_out  = (const float*)d_in[7];
    const float* b_out  = (const float*)d_in[8];
    const float* conn_w = (const float*)d_in[9];
    const float* conn_b = (const float*)d_in[10];
    const float* dec_w  = (const float*)d_in[11];
    const float* dec_b  = (const float*)d_in[12];
    float* out = (float*)d_out;

    int8_t *spikes, *sa, *sb;
    float *x3, *w1t, *w2t, *wot;
    cudaGetSymbolAddress((void**)&spikes, g_spikes);
    cudaGetSymbolAddress((void**)&sa,  g_sa);
    cudaGetSymbolAddress((void**)&sb,  g_sb);
    cudaGetSymbolAddress((void**)&x3,  g_x3);
    cudaGetSymbolAddress((void**)&w1t, g_w1t);
    cudaGetSymbolAddress((void**)&w2t, g_w2t);
    cudaGetSymbolAddress((void**)&wot, g_wot);

    const int smemG = 32 * 128 * 8 + 2 * 32 * 128 * 4;  // 65536
    cudaFuncSetAttribute(gemm_f2<640, 1>,  cudaFuncAttributeMaxDynamicSharedMemorySize, smemG);
    cudaFuncSetAttribute(gemm_f2<1024, 1>, cudaFuncAttributeMaxDynamicSharedMemorySize, smemG);
    cudaFuncSetAttribute(gemm_f2<1024, 0>, cudaFuncAttributeMaxDynamicSharedMemorySize, smemG);

    {
        dim3 tb(32, 8);
        transpose_w<<<dim3(32, 20), tb>>>(w1, w1t, H_, IN_, H_);
        transpose_w<<<dim3(32, 32), tb>>>(w2, w2t, H_, H_, H_);
        transpose_w<<<dim3(8, 32),  tb>>>(w_out, wot, OUT_, H_, 256);
    }
    encoder_kernel<<<(B_ * IN_ + 255) / 256, 256>>>(obs, mean, stdv);

    // L1: s1 = scan(spikes_all @ W1)   (M=32768, K=640, N=1024, fused scan)
    gemm_f2<640, 1><<<dim3(8, M_ / 128), 256, smemG>>>(
        spikes, w1t, b1, nullptr, sa, H_, H_, H_);

    // L2: s2 = scan(s1_all @ W2)       (M=32768, K=1024, N=1024, fused scan)
    gemm_f2<1024, 1><<<dim3(8, M_ / 128), 256, smemG>>>(
        sa, w2t, b2, nullptr, sb, H_, H_, H_);

    // L3: X3 = s2_all @ Wout           (M=32768, K=1024, N=160 padded 256)
    gemm_f2<1024, 0><<<dim3(2, M_ / 128), 256, smemG>>>(
        sb, wot, nullptr, x3, nullptr, 256, OUT_, OUT_);

    // output scan: lateral + neuron + fr + decode
    scan_out<<<(B_ * AD_ + 255) / 256, 256>>>(x3, b_out, conn_w, conn_b, dec_w, dec_b, out);
}

// round 14
// speedup vs baseline: 1.3174x; 1.3174x over previous
#include <cuda_runtime.h>
#include <cstdint>

// ---------------- problem constants ----------------
#define B_     4096
#define OBS_   64
#define EP_    10
#define IN_    640      // OBS*EP
#define H_     1024
#define AD_    16
#define DP_    10
#define OUT_   160      // AD*DP
#define T_     8
#define M_     (B_ * T_)   // 32768 batched rows, ordered m = b*8 + t

#define CDECAY 0.5f
#define VTH    0.5f
#define THV   (-0.172f)
#define THU    0.529f
#define THR    0.021f
#define THS    0.132f

// ---------------- device scratch ----------------
__device__ __align__(128) int8_t g_spikes[(size_t)M_ * (size_t)IN_];   // 21 MB, [b*8+t][i]
__device__ __align__(128) int8_t g_sa[(size_t)M_ * (size_t)H_];        // 33.5 MB
__device__ __align__(128) int8_t g_sb[(size_t)M_ * (size_t)H_];        // 33.5 MB
__device__ __align__(128) float g_x3[(size_t)M_ * (size_t)OUT_];       // 21 MB
__device__ __align__(128) float g_w1t[(size_t)IN_ * (size_t)H_];   // [640][1024]
__device__ __align__(128) float g_w2t[(size_t)H_ * (size_t)H_];    // [1024][1024]
__device__ __align__(128) float g_wot[(size_t)H_ * 256];           // [1024][256], cols>=160 zero

// ---------------- helpers ----------------
__device__ __forceinline__ uint32_t smem_u32(const void* p) {
    uint32_t a;
    asm("{ .reg .u64 t; cvta.to.shared.u64 t, %1; cvt.u32.u64 %0, t; }" : "=r"(a) : "l"(p));
    return a;
}
__device__ __forceinline__ void cp_async16(uint32_t saddr, const void* g) {
    asm volatile("cp.async.cg.shared.global [%0], [%1], 16;" :: "r"(saddr), "l"(g));
}
#define CP_COMMIT() asm volatile("cp.async.commit_group;" ::: "memory")
#define CP_WAIT0()  asm volatile("cp.async.wait_group 0;" ::: "memory")

__device__ __forceinline__ void lds_v2u64(unsigned long long& a, unsigned long long& b, uint32_t addr) {
    asm volatile("ld.shared.v2.u64 {%0,%1}, [%2];" : "=l"(a), "=l"(b) : "r"(addr));
}
__device__ __forceinline__ void lds_f4(float4& v, uint32_t addr) {
    asm volatile("ld.shared.v4.f32 {%0,%1,%2,%3}, [%4];"
        : "=f"(v.x), "=f"(v.y), "=f"(v.z), "=f"(v.w) : "r"(addr));
}
__device__ __forceinline__ void sts32(uint32_t addr, uint32_t d) {
    asm volatile("st.shared.b32 [%0], %1;" :: "r"(addr), "r"(d));
}
__device__ __forceinline__ unsigned long long dup2(float x) {
    unsigned long long d;
    uint32_t u = __float_as_uint(x);
    asm("mov.b64 %0, {%1,%1};" : "=l"(d) : "r"(u));
    return d;
}
// packed fp32 pair FMA: per-lane IEEE RN fp32 fma (bitwise == scalar FFMA chain)
__device__ __forceinline__ void fma2(unsigned long long& d, unsigned long long a, unsigned long long b) {
    asm("fma.rn.f32x2 %0, %1, %2, %0;" : "+l"(d) : "l"(a), "l"(b));
}
__device__ __forceinline__ float f2lo(unsigned long long u) {
    return __int_as_float((int)(unsigned)(u & 0xffffffffull));
}
__device__ __forceinline__ float f2hi(unsigned long long u) {
    return __int_as_float((int)(unsigned)(u >> 32));
}

// ---------------- batched f32x2 GEMM, sequential-k fp32 semantics ----------------
// X[m][n] = sum_{k ascending} A[m][k]*W[n][k], fp32 RN FMA chain per output.
// A: s8 spikes [M][KBASE], m = b*8+t. WT: fp32 [KBASE][WLD] k-major.
// CTA 128x128, BK=32, 256 threads; thread: 16 rows (2 batches x t0..7) x 4 cols.
// f32x2 acc lanes = TWO ADJACENT ROWS (natural pairs from plain-f32 A smem,
// full-warp broadcast); W duplicated in regs (only 4 dup2/k).
// Per k: 4 LDS(A) + 1 LDS(W) + 4 MOV + 32 fma2.
// Smem 64KB: A plain [2][32][128] f32 (bit-expanded); W [2][32][128] cp.async.
// MODE 0: plain store to X. MODE 1: fused hidden-neuron scan over t, write s8 spikes.
template<int KBASE, int MODE>
__global__ __launch_bounds__(256, 2) void gemm_f2(
    const int8_t* __restrict__ A, const float* __restrict__ WT,
    const float* __restrict__ bias,
    float* __restrict__ X, int8_t* __restrict__ S,
    int WLD, int XLD, int NTOT) {

    constexpr int KT = KBASE / 32;
    constexpr uint32_t ABUF = 32 * 128 * 4;
    constexpr uint32_t WBUF = 32 * 128 * 4;

    extern __shared__ char smraw[];
    const uint32_t ab0 = smem_u32(smraw);
    const uint32_t wb0 = ab0 + 2 * ABUF;

    const int tid  = threadIdx.x;
    const int trow = tid >> 5;     // 0..7   (16 rows each)
    const int tcol = tid & 31;     // 0..31  (4 cols each)
    const int bm0 = blockIdx.y * 128;
    const int bn0 = blockIdx.x * 128;

    const int arowi = tid & 127;
    const int khalf = tid >> 7;    // 0/1
    const int8_t* arow = A + (size_t)(bm0 + arowi) * KBASE + khalf * 16;

    uint4 arg;
    auto ldgA = [&](int t) { arg = *(const uint4*)(arow + t * 32); };
    auto cpW = [&](int t) {
        const float* src = WT + (size_t)(t * 32) * WLD + bn0;
        const uint32_t dst = wb0 + (uint32_t)(t & 1) * WBUF;
#pragma unroll
        for (int q = 0; q < 4; q++) {
            int ch = tid + q * 256;           // 0..1023
            int row = ch >> 5, c16 = ch & 31; // 32 rows x 32 16B-chunks
            cp_async16(dst + (uint32_t)(row * 128 + c16 * 4) * 4,
                       src + (size_t)row * WLD + c16 * 4);
        }
        CP_COMMIT();
    };
    auto stsA = [&](int t) {
        uint32_t base = ab0 + (uint32_t)(t & 1) * ABUF
                      + (uint32_t)(khalf * 16 * 128 + arowi) * 4u;
#pragma unroll
        for (int w = 0; w < 4; w++) {
            uint32_t x = ((const uint32_t*)&arg)[w];
#pragma unroll
            for (int b = 0; b < 4; b++)
                sts32(base + (uint32_t)((w * 4 + b) * 128) * 4u,
                      ((x >> (8 * b)) & 1u) * 0x3f800000u);
        }
    };

    // acc[p][c]: f32x2 over rows (2p, 2p+1), col c
    unsigned long long acc[8][4];
#pragma unroll
    for (int p = 0; p < 8; p++)
#pragma unroll
        for (int c = 0; c < 4; c++) acc[p][c] = 0ull;

    // prologue
    ldgA(0); cpW(0); stsA(0);

    for (int i = 0; i < KT; i++) {
        CP_WAIT0();
        __syncthreads();
        if (i + 1 < KT) { cpW(i + 1); ldgA(i + 1); }

        const uint32_t ab = ab0 + (uint32_t)(i & 1) * ABUF + (uint32_t)(trow * 16) * 4u;
        const uint32_t wb = wb0 + (uint32_t)(i & 1) * WBUF + (uint32_t)(tcol * 4) * 4u;
#pragma unroll
        for (int k = 0; k < 32; k++) {
            unsigned long long ap[8];
            const uint32_t ak = ab + (uint32_t)(k * 128) * 4u;
            lds_v2u64(ap[0], ap[1], ak);
            lds_v2u64(ap[2], ap[3], ak + 16u);
            lds_v2u64(ap[4], ap[5], ak + 32u);
            lds_v2u64(ap[6], ap[7], ak + 48u);
            float4 w4;
            lds_f4(w4, wb + (uint32_t)(k * 128) * 4u);
            unsigned long long wd[4];
            wd[0] = dup2(w4.x); wd[1] = dup2(w4.y);
            wd[2] = dup2(w4.z); wd[3] = dup2(w4.w);
#pragma unroll
            for (int p = 0; p < 8; p++)
#pragma unroll
                for (int c = 0; c < 4; c++) fma2(acc[p][c], ap[p], wd[c]);
        }
        if (i + 1 < KT) stsA(i + 1);
    }

    if (MODE == 1) {
        // fused hidden-neuron scan: thread rows = 2 batch groups x t 0..7
        float bj[4];
#pragma unroll
        for (int c = 0; c < 4; c++) bj[c] = bias[bn0 + tcol * 4 + c];
        uint32_t srow[16];
#pragma unroll
        for (int i = 0; i < 16; i++) srow[i] = 0u;
#pragma unroll
        for (int c = 0; c < 4; c++) {
#pragma unroll
            for (int g = 0; g < 2; g++) {
                float cu = 0.0f, vv = 0.0f, rr = 0.0f, ss = 0.0f;
#pragma unroll
                for (int t = 0; t < T_; t++) {
                    unsigned long long a = acc[g * 4 + (t >> 1)][c];
                    float xv = (t & 1) ? f2hi(a) : f2lo(a);
                    cu = cu * CDECAY + xv + bj[c];
                    vv = vv * (1.0f - ss) + ss * THR;
                    rr = rr + ss * THS;
                    float vd = vv * vv - vv - rr + cu;
                    float rd = THV * vv - THU * rr;
                    vv += vd; rr += rd;
                    ss = vv > VTH ? 1.0f : 0.0f;
                    srow[g * 8 + t] |= (ss != 0.0f ? 1u : 0u) << (8 * c);
                }
            }
        }
#pragma unroll
        for (int i = 0; i < 16; i++) {
            size_t row = (size_t)(bm0 + trow * 16 + i);
            *(uint32_t*)&S[row * H_ + bn0 + tcol * 4] = srow[i];
        }
    } else {
#pragma unroll
        for (int i = 0; i < 16; i++) {
            int row = bm0 + trow * 16 + i;
            int col = bn0 + tcol * 4;
            if (col < NTOT) {
                const int p = i >> 1, e = i & 1;
                float4 v;
                v.x = e ? f2hi(acc[p][0]) : f2lo(acc[p][0]);
                v.y = e ? f2hi(acc[p][1]) : f2lo(acc[p][1]);
                v.z = e ? f2hi(acc[p][2]) : f2lo(acc[p][2]);
                v.w = e ? f2hi(acc[p][3]) : f2lo(acc[p][3]);
                *(float4*)&X[(size_t)row * XLD + col] = v;
            }
        }
    }
}

// ---------------- weight transpose: w[N][K] -> wt[K][NP], zero-pad n>=N ----------------
__global__ void transpose_w(const float* __restrict__ w, float* __restrict__ wt,
                            int N, int K, int NP) {
    __shared__ float t[32][33];
    int tx = threadIdx.x, ty = threadIdx.y;  // 32 x 8
    int bx = blockIdx.x, by = blockIdx.y;
#pragma unroll
    for (int j = 0; j < 4; j++) {
        int n = bx * 32 + ty + j * 8;
        int k = by * 32 + tx;
        t[ty + j * 8][tx] = (n < N) ? w[(size_t)n * K + k] : 0.0f;
    }
    __syncthreads();
#pragma unroll
    for (int j = 0; j < 4; j++) {
        int k = by * 32 + ty + j * 8;
        int n = bx * 32 + tx;
        wt[(size_t)k * NP + n] = t[tx][ty + j * 8];
    }
}

// ---------------- encoder (writes spikes in m = b*8+t order) ----------------
__global__ void encoder_kernel(const float* __restrict__ obs,
                               const float* __restrict__ mean,
                               const float* __restrict__ stdv) {
    int idx = blockIdx.x * blockDim.x + threadIdx.x;
    if (idx >= B_ * IN_) return;
    int b = idx / IN_;
    int i = idx - b * IN_;
    int o = i / EP_;
    float d  = obs[b * OBS_ + o] - mean[i];
    float sd = stdv[i];
    float a  = expf(-0.5f * d * d / (sd * sd));
    float volt = 0.0f;
    int8_t* sp = g_spikes + (size_t)b * T_ * IN_ + i;
#pragma unroll
    for (int t = 0; t < T_; t++) {
        volt += a;
        float s = volt > 1.0f ? 1.0f : 0.0f;
        volt -= s;
        sp[(size_t)t * IN_] = (int8_t)s;
    }
}

// ---------------- output-layer scan: lateral conv + neuron + fr + decode ----------------
__global__ __launch_bounds__(256) void scan_out(
    const float* __restrict__ x3, const float* __restrict__ b_out,
    const float* __restrict__ conn_w, const float* __restrict__ conn_b,
    const float* __restrict__ dec_w, const float* __restrict__ dec_b,
    float* __restrict__ out) {
    __shared__ float cw[AD_ * DP_ * DP_];   // 1600
    for (int i = threadIdx.x; i < AD_ * DP_ * DP_; i += blockDim.x) cw[i] = conn_w[i];
    __syncthreads();

    int idx = blockIdx.x * blockDim.x + threadIdx.x;   // (b, a)
    if (idx >= B_ * AD_) return;
    int b = idx >> 4;
    int a = idx & 15;

    float cb[DP_], bo[DP_];
#pragma unroll
    for (int j = 0; j < DP_; j++) {
        cb[j] = conn_b[a * DP_ + j];
        bo[j] = b_out[a * DP_ + j];
    }
    const float* cwa = cw + a * DP_ * DP_;

    float cur[DP_], vv[DP_], rr[DP_], sp[DP_], fr[DP_];
#pragma unroll
    for (int j = 0; j < DP_; j++) { cur[j] = 0.f; vv[j] = 0.f; rr[j] = 0.f; sp[j] = 0.f; fr[j] = 0.f; }

    for (int t = 0; t < T_; t++) {
        const float* xp = x3 + ((size_t)b * T_ + t) * OUT_ + a * DP_;
        float sn[DP_];
#pragma unroll
        for (int j = 0; j < DP_; j++) {
            float lat = cb[j];
#pragma unroll
            for (int k = 0; k < DP_; k++) lat += sp[k] * cwa[j * DP_ + k];
            float c  = cur[j] * CDECAY + xp[j] + bo[j] + lat;
            float v2 = vv[j] * (1.0f - sp[j]) + sp[j] * THR;
            float r2 = rr[j] + sp[j] * THS;
            float vd = v2 * v2 - v2 - r2 + c;
            float rd = THV * v2 - THU * r2;
            v2 += vd; r2 += rd;
            sn[j] = v2 > VTH ? 1.0f : 0.0f;
            cur[j] = c; vv[j] = v2; rr[j] = r2;
        }
#pragma unroll
        for (int j = 0; j < DP_; j++) { sp[j] = sn[j]; fr[j] += sn[j]; }
    }

    float raw = dec_b[a];
#pragma unroll
    for (int p = 0; p < DP_; p++) raw += (fr[p] * 0.125f) * dec_w[a * DP_ + p];
    out[idx] = tanhf(raw);
}

// ---------------- launch ----------------
extern "C" void kernel_launch(void* const* d_in, const int* in_sizes, int n_in,
                              void* d_out, int out_size) {
    const float* obs    = (const float*)d_in[0];
    const float* mean   = (const float*)d_in[1];
    const float* stdv   = (const float*)d_in[2];
    const float* w1     = (const float*)d_in[3];
    const float* b1     = (const float*)d_in[4];
    const float* w2     = (const float*)d_in[5];
    const float* b2     = (const float*)d_in[6];
    const float* w_out  = (const float*)d_in[7];
    const float* b_out  = (const float*)d_in[8];
    const float* conn_w = (const float*)d_in[9];
    const float* conn_b = (const float*)d_in[10];
    const float* dec_w  = (const float*)d_in[11];
    const float* dec_b  = (const float*)d_in[12];
    float* out = (float*)d_out;

    int8_t *spikes, *sa, *sb;
    float *x3, *w1t, *w2t, *wot;
    cudaGetSymbolAddress((void**)&spikes, g_spikes);
    cudaGetSymbolAddress((void**)&sa,  g_sa);
    cudaGetSymbolAddress((void**)&sb,  g_sb);
    cudaGetSymbolAddress((void**)&x3,  g_x3);
    cudaGetSymbolAddress((void**)&w1t, g_w1t);
    cudaGetSymbolAddress((void**)&w2t, g_w2t);
    cudaGetSymbolAddress((void**)&wot, g_wot);

    const int smemG = 2 * 32 * 128 * 4 + 2 * 32 * 128 * 4;  // 65536
    cudaFuncSetAttribute(gemm_f2<640, 1>,  cudaFuncAttributeMaxDynamicSharedMemorySize, smemG);
    cudaFuncSetAttribute(gemm_f2<1024, 1>, cudaFuncAttributeMaxDynamicSharedMemorySize, smemG);
    cudaFuncSetAttribute(gemm_f2<1024, 0>, cudaFuncAttributeMaxDynamicSharedMemorySize, smemG);

    {
        dim3 tb(32, 8);
        transpose_w<<<dim3(32, 20), tb>>>(w1, w1t, H_, IN_, H_);
        transpose_w<<<dim3(32, 32), tb>>>(w2, w2t, H_, H_, H_);
        transpose_w<<<dim3(8, 32),  tb>>>(w_out, wot, OUT_, H_, 256);
    }
    encoder_kernel<<<(B_ * IN_ + 255) / 256, 256>>>(obs, mean, stdv);

    // L1: s1 = scan(spikes_all @ W1)   (M=32768, K=640, N=1024, fused scan)
    gemm_f2<640, 1><<<dim3(8, M_ / 128), 256, smemG>>>(
        spikes, w1t, b1, nullptr, sa, H_, H_, H_);

    // L2: s2 = scan(s1_all @ W2)       (M=32768, K=1024, N=1024, fused scan)
    gemm_f2<1024, 1><<<dim3(8, M_ / 128), 256, smemG>>>(
        sa, w2t, b2, nullptr, sb, H_, H_, H_);

    // L3: X3 = s2_all @ Wout           (M=32768, K=1024, N=160 padded 256)
    gemm_f2<1024, 0><<<dim3(2, M_ / 128), 256, smemG>>>(
        sb, wot, nullptr, x3, nullptr, 256, OUT_, OUT_);

    // output scan: lateral + neuron + fr + decode
    scan_out<<<(B_ * AD_ + 255) / 256, 256>>>(x3, b_out, conn_w, conn_b, dec_w, dec_b, out);
}

// round 15
// speedup vs baseline: 1.3799x; 1.0475x over previous
#include <cuda_runtime.h>
#include <cstdint>

// ---------------- problem constants ----------------
#define B_     4096
#define OBS_   64
#define EP_    10
#define IN_    640      // OBS*EP
#define H_     1024
#define AD_    16
#define DP_    10
#define OUT_   160      // AD*DP
#define T_     8
#define M_     (B_ * T_)   // 32768 batched rows, ordered m = b*8 + t

#define CDECAY 0.5f
#define VTH    0.5f
#define THV   (-0.172f)
#define THU    0.529f
#define THR    0.021f
#define THS    0.132f

// ---------------- device scratch ----------------
__device__ __align__(128) int8_t g_spikes[(size_t)M_ * (size_t)IN_];   // 21 MB, [b*8+t][i]
__device__ __align__(128) int8_t g_sa[(size_t)M_ * (size_t)H_];        // 33.5 MB
__device__ __align__(128) int8_t g_sb[(size_t)M_ * (size_t)H_];        // 33.5 MB
__device__ __align__(128) float g_x3[(size_t)M_ * (size_t)OUT_];       // 21 MB
__device__ __align__(128) float g_w1t[(size_t)IN_ * (size_t)H_];   // [640][1024]
__device__ __align__(128) float g_w2t[(size_t)H_ * (size_t)H_];    // [1024][1024]
__device__ __align__(128) float g_wot[(size_t)H_ * (size_t)OUT_];  // [1024][160]

// ---------------- helpers ----------------
__device__ __forceinline__ uint32_t smem_u32(const void* p) {
    uint32_t a;
    asm("{ .reg .u64 t; cvta.to.shared.u64 t, %1; cvt.u32.u64 %0, t; }" : "=r"(a) : "l"(p));
    return a;
}
__device__ __forceinline__ void cp_async16(uint32_t saddr, const void* g) {
    asm volatile("cp.async.cg.shared.global [%0], [%1], 16;" :: "r"(saddr), "l"(g));
}
#define CP_COMMIT() asm volatile("cp.async.commit_group;" ::: "memory")
#define CP_WAIT0()  asm volatile("cp.async.wait_group 0;" ::: "memory")

__device__ __forceinline__ void lds_v2u64(unsigned long long& a, unsigned long long& b, uint32_t addr) {
    asm volatile("ld.shared.v2.u64 {%0,%1}, [%2];" : "=l"(a), "=l"(b) : "r"(addr));
}
__device__ __forceinline__ void lds_f4(float4& v, uint32_t addr) {
    asm volatile("ld.shared.v4.f32 {%0,%1,%2,%3}, [%4];"
        : "=f"(v.x), "=f"(v.y), "=f"(v.z), "=f"(v.w) : "r"(addr));
}
__device__ __forceinline__ float lds_f1(uint32_t addr) {
    float v;
    asm volatile("ld.shared.f32 %0, [%1];" : "=f"(v) : "r"(addr));
    return v;
}
__device__ __forceinline__ void sts32(uint32_t addr, uint32_t d) {
    asm volatile("st.shared.b32 [%0], %1;" :: "r"(addr), "r"(d));
}
__device__ __forceinline__ unsigned long long dup2(float x) {
    unsigned long long d;
    uint32_t u = __float_as_uint(x);
    asm("mov.b64 %0, {%1,%1};" : "=l"(d) : "r"(u));
    return d;
}
// packed fp32 pair FMA: per-lane IEEE RN fp32 fma (bitwise == scalar FFMA chain)
__device__ __forceinline__ void fma2(unsigned long long& d, unsigned long long a, unsigned long long b) {
    asm("fma.rn.f32x2 %0, %1, %2, %0;" : "+l"(d) : "l"(a), "l"(b));
}
__device__ __forceinline__ float f2lo(unsigned long long u) {
    return __int_as_float((int)(unsigned)(u & 0xffffffffull));
}
__device__ __forceinline__ float f2hi(unsigned long long u) {
    return __int_as_float((int)(unsigned)(u >> 32));
}

// ---------------- batched f32x2 GEMM (BN=128), sequential-k fp32 semantics ----------------
// X[m][n] = sum_{k ascending} A[m][k]*W[n][k], fp32 RN FMA chain per output.
// A: s8 spikes [M][KBASE], m = b*8+t. WT: fp32 [KBASE][WLD] k-major.
// CTA 128x128, BK=32, 256 threads; thread: 16 rows (2 batches x t0..7) x 4 cols.
// f32x2 acc lanes = two adjacent rows (natural pairs from plain-f32 A smem).
// MODE 0: plain store to X. MODE 1: fused hidden-neuron scan over t, write s8 spikes.
template<int KBASE, int MODE>
__global__ __launch_bounds__(256, 2) void gemm_f2(
    const int8_t* __restrict__ A, const float* __restrict__ WT,
    const float* __restrict__ bias,
    float* __restrict__ X, int8_t* __restrict__ S,
    int WLD, int XLD, int NTOT) {

    constexpr int KT = KBASE / 32;
    constexpr uint32_t ABUF = 32 * 128 * 4;
    constexpr uint32_t WBUF = 32 * 128 * 4;

    extern __shared__ char smraw[];
    const uint32_t ab0 = smem_u32(smraw);
    const uint32_t wb0 = ab0 + 2 * ABUF;

    const int tid  = threadIdx.x;
    const int trow = tid >> 5;     // 0..7   (16 rows each)
    const int tcol = tid & 31;     // 0..31  (4 cols each)
    const int bm0 = blockIdx.y * 128;
    const int bn0 = blockIdx.x * 128;

    const int arowi = tid & 127;
    const int khalf = tid >> 7;    // 0/1
    const int8_t* arow = A + (size_t)(bm0 + arowi) * KBASE + khalf * 16;

    uint4 arg;
    auto ldgA = [&](int t) { arg = *(const uint4*)(arow + t * 32); };
    auto cpW = [&](int t) {
        const float* src = WT + (size_t)(t * 32) * WLD + bn0;
        const uint32_t dst = wb0 + (uint32_t)(t & 1) * WBUF;
#pragma unroll
        for (int q = 0; q < 4; q++) {
            int ch = tid + q * 256;           // 0..1023
            int row = ch >> 5, c16 = ch & 31; // 32 rows x 32 16B-chunks
            cp_async16(dst + (uint32_t)(row * 128 + c16 * 4) * 4,
                       src + (size_t)row * WLD + c16 * 4);
        }
        CP_COMMIT();
    };
    auto stsA = [&](int t) {
        uint32_t base = ab0 + (uint32_t)(t & 1) * ABUF
                      + (uint32_t)(khalf * 16 * 128 + arowi) * 4u;
#pragma unroll
        for (int w = 0; w < 4; w++) {
            uint32_t x = ((const uint32_t*)&arg)[w];
#pragma unroll
            for (int b = 0; b < 4; b++)
                sts32(base + (uint32_t)((w * 4 + b) * 128) * 4u,
                      ((x >> (8 * b)) & 1u) * 0x3f800000u);
        }
    };

    // acc[p][c]: f32x2 over rows (2p, 2p+1), col c
    unsigned long long acc[8][4];
#pragma unroll
    for (int p = 0; p < 8; p++)
#pragma unroll
        for (int c = 0; c < 4; c++) acc[p][c] = 0ull;

    // prologue
    ldgA(0); cpW(0); stsA(0);

    for (int i = 0; i < KT; i++) {
        CP_WAIT0();
        __syncthreads();
        if (i + 1 < KT) { cpW(i + 1); ldgA(i + 1); }

        const uint32_t ab = ab0 + (uint32_t)(i & 1) * ABUF + (uint32_t)(trow * 16) * 4u;
        const uint32_t wb = wb0 + (uint32_t)(i & 1) * WBUF + (uint32_t)(tcol * 4) * 4u;
#pragma unroll
        for (int k = 0; k < 32; k++) {
            unsigned long long ap[8];
            const uint32_t ak = ab + (uint32_t)(k * 128) * 4u;
            lds_v2u64(ap[0], ap[1], ak);
            lds_v2u64(ap[2], ap[3], ak + 16u);
            lds_v2u64(ap[4], ap[5], ak + 32u);
            lds_v2u64(ap[6], ap[7], ak + 48u);
            float4 w4;
            lds_f4(w4, wb + (uint32_t)(k * 128) * 4u);
            unsigned long long wd[4];
            wd[0] = dup2(w4.x); wd[1] = dup2(w4.y);
            wd[2] = dup2(w4.z); wd[3] = dup2(w4.w);
#pragma unroll
            for (int p = 0; p < 8; p++)
#pragma unroll
                for (int c = 0; c < 4; c++) fma2(acc[p][c], ap[p], wd[c]);
        }
        if (i + 1 < KT) stsA(i + 1);
    }

    if (MODE == 1) {
        // fused hidden-neuron scan: thread rows = 2 batch groups x t 0..7
        float bj[4];
#pragma unroll
        for (int c = 0; c < 4; c++) bj[c] = bias[bn0 + tcol * 4 + c];
        uint32_t srow[16];
#pragma unroll
        for (int i = 0; i < 16; i++) srow[i] = 0u;
#pragma unroll
        for (int c = 0; c < 4; c++) {
#pragma unroll
            for (int g = 0; g < 2; g++) {
                float cu = 0.0f, vv = 0.0f, rr = 0.0f, ss = 0.0f;
#pragma unroll
                for (int t = 0; t < T_; t++) {
                    unsigned long long a = acc[g * 4 + (t >> 1)][c];
                    float xv = (t & 1) ? f2hi(a) : f2lo(a);
                    cu = cu * CDECAY + xv + bj[c];
                    vv = vv * (1.0f - ss) + ss * THR;
                    rr = rr + ss * THS;
                    float vd = vv * vv - vv - rr + cu;
                    float rd = THV * vv - THU * rr;
                    vv += vd; rr += rd;
                    ss = vv > VTH ? 1.0f : 0.0f;
                    srow[g * 8 + t] |= (ss != 0.0f ? 1u : 0u) << (8 * c);
                }
            }
        }
#pragma unroll
        for (int i = 0; i < 16; i++) {
            size_t row = (size_t)(bm0 + trow * 16 + i);
            *(uint32_t*)&S[row * H_ + bn0 + tcol * 4] = srow[i];
        }
    } else {
#pragma unroll
        for (int i = 0; i < 16; i++) {
            int row = bm0 + trow * 16 + i;
            int col = bn0 + tcol * 4;
            if (col < NTOT) {
                const int p = i >> 1, e = i & 1;
                float4 v;
                v.x = e ? f2hi(acc[p][0]) : f2lo(acc[p][0]);
                v.y = e ? f2hi(acc[p][1]) : f2lo(acc[p][1]);
                v.z = e ? f2hi(acc[p][2]) : f2lo(acc[p][2]);
                v.w = e ? f2hi(acc[p][3]) : f2lo(acc[p][3]);
                *(float4*)&X[(size_t)row * XLD + col] = v;
            }
        }
    }
}

// ---------------- L3 GEMM: BN=160 exact (no padded columns) ----------------
// CTA 128 x 160, grid (1, M/128). Thread: 16 rows x 5 cols, cols = tcol + c*32.
// W smem [2][32][160] f32 (cp.async), A identical to gemm_f2. Writes x3 [M][160].
__global__ __launch_bounds__(256, 2) void gemm_f2_l3(
    const int8_t* __restrict__ A, const float* __restrict__ WT,
    float* __restrict__ X) {

    constexpr int KB = 1024, KT = KB / 32;
    constexpr uint32_t ABUF = 32 * 128 * 4;
    constexpr uint32_t WBUF = 32 * 160 * 4;

    extern __shared__ char smraw[];
    const uint32_t ab0 = smem_u32(smraw);
    const uint32_t wb0 = ab0 + 2 * ABUF;

    const int tid  = threadIdx.x;
    const int trow = tid >> 5;     // 0..7
    const int tcol = tid & 31;     // 0..31
    const int bm0 = blockIdx.y * 128;

    const int arowi = tid & 127;
    const int khalf = tid >> 7;
    const int8_t* arow = A + (size_t)(bm0 + arowi) * KB + khalf * 16;

    uint4 arg;
    auto ldgA = [&](int t) { arg = *(const uint4*)(arow + t * 32); };
    auto cpW = [&](int t) {
        const float* src = WT + (size_t)(t * 32) * OUT_;
        const uint32_t dst = wb0 + (uint32_t)(t & 1) * WBUF;
#pragma unroll
        for (int q = 0; q < 5; q++) {
            int ch = tid + q * 256;          // 0..1279
            int row = ch / 40, c16 = ch % 40; // 32 rows x 40 16B-chunks
            cp_async16(dst + (uint32_t)(row * 160 + c16 * 4) * 4,
                       src + (size_t)row * OUT_ + c16 * 4);
        }
        CP_COMMIT();
    };
    auto stsA = [&](int t) {
        uint32_t base = ab0 + (uint32_t)(t & 1) * ABUF
                      + (uint32_t)(khalf * 16 * 128 + arowi) * 4u;
#pragma unroll
        for (int w = 0; w < 4; w++) {
            uint32_t x = ((const uint32_t*)&arg)[w];
#pragma unroll
            for (int b = 0; b < 4; b++)
                sts32(base + (uint32_t)((w * 4 + b) * 128) * 4u,
                      ((x >> (8 * b)) & 1u) * 0x3f800000u);
        }
    };

    unsigned long long acc[8][5];
#pragma unroll
    for (int p = 0; p < 8; p++)
#pragma unroll
        for (int c = 0; c < 5; c++) acc[p][c] = 0ull;

    ldgA(0); cpW(0); stsA(0);

    for (int i = 0; i < KT; i++) {
        CP_WAIT0();
        __syncthreads();
        if (i + 1 < KT) { cpW(i + 1); ldgA(i + 1); }

        const uint32_t ab = ab0 + (uint32_t)(i & 1) * ABUF + (uint32_t)(trow * 16) * 4u;
        const uint32_t wb = wb0 + (uint32_t)(i & 1) * WBUF + (uint32_t)tcol * 4u;
#pragma unroll
        for (int k = 0; k < 32; k++) {
            unsigned long long ap[8];
            const uint32_t ak = ab + (uint32_t)(k * 128) * 4u;
            lds_v2u64(ap[0], ap[1], ak);
            lds_v2u64(ap[2], ap[3], ak + 16u);
            lds_v2u64(ap[4], ap[5], ak + 32u);
            lds_v2u64(ap[6], ap[7], ak + 48u);
            const uint32_t wk = wb + (uint32_t)(k * 160) * 4u;
            unsigned long long wd[5];
#pragma unroll
            for (int c = 0; c < 5; c++) wd[c] = dup2(lds_f1(wk + (uint32_t)(c * 32) * 4u));
#pragma unroll
            for (int p = 0; p < 8; p++)
#pragma unroll
                for (int c = 0; c < 5; c++) fma2(acc[p][c], ap[p], wd[c]);
        }
        if (i + 1 < KT) stsA(i + 1);
    }

    // epilogue: scalar stores, cols tcol + c*32
#pragma unroll
    for (int i = 0; i < 16; i++) {
        int row = bm0 + trow * 16 + i;
        const int p = i >> 1, e = i & 1;
        float* xr = X + (size_t)row * OUT_ + tcol;
#pragma unroll
        for (int c = 0; c < 5; c++)
            xr[c * 32] = e ? f2hi(acc[p][c]) : f2lo(acc[p][c]);
    }
}

// ---------------- weight transpose: w[N][K] -> wt[K][NP], zero-pad n>=N ----------------
__global__ void transpose_w(const float* __restrict__ w, float* __restrict__ wt,
                            int N, int K, int NP) {
    __shared__ float t[32][33];
    int tx = threadIdx.x, ty = threadIdx.y;  // 32 x 8
    int bx = blockIdx.x, by = blockIdx.y;
#pragma unroll
    for (int j = 0; j < 4; j++) {
        int n = bx * 32 + ty + j * 8;
        int k = by * 32 + tx;
        t[ty + j * 8][tx] = (n < N) ? w[(size_t)n * K + k] : 0.0f;
    }
    __syncthreads();
#pragma unroll
    for (int j = 0; j < 4; j++) {
        int k = by * 32 + ty + j * 8;
        int n = bx * 32 + tx;
        if (n < NP) wt[(size_t)k * NP + n] = t[tx][ty + j * 8];
    }
}

// ---------------- encoder (writes spikes in m = b*8+t order) ----------------
__global__ void encoder_kernel(const float* __restrict__ obs,
                               const float* __restrict__ mean,
                               const float* __restrict__ stdv) {
    int idx = blockIdx.x * blockDim.x + threadIdx.x;
    if (idx >= B_ * IN_) return;
    int b = idx / IN_;
    int i = idx - b * IN_;
    int o = i / EP_;
    float d  = obs[b * OBS_ + o] - mean[i];
    float sd = stdv[i];
    float a  = expf(-0.5f * d * d / (sd * sd));
    float volt = 0.0f;
    int8_t* sp = g_spikes + (size_t)b * T_ * IN_ + i;
#pragma unroll
    for (int t = 0; t < T_; t++) {
        volt += a;
        float s = volt > 1.0f ? 1.0f : 0.0f;
        volt -= s;
        sp[(size_t)t * IN_] = (int8_t)s;
    }
}

// ---------------- output-layer scan: lateral conv + neuron + fr + decode ----------------
__global__ __launch_bounds__(256) void scan_out(
    const float* __restrict__ x3, const float* __restrict__ b_out,
    const float* __restrict__ conn_w, const float* __restrict__ conn_b,
    const float* __restrict__ dec_w, const float* __restrict__ dec_b,
    float* __restrict__ out) {
    __shared__ float cw[AD_ * DP_ * DP_];   // 1600
    for (int i = threadIdx.x; i < AD_ * DP_ * DP_; i += blockDim.x) cw[i] = conn_w[i];
    __syncthreads();

    int idx = blockIdx.x * blockDim.x + threadIdx.x;   // (b, a)
    if (idx >= B_ * AD_) return;
    int b = idx >> 4;
    int a = idx & 15;

    float cb[DP_], bo[DP_];
#pragma unroll
    for (int j = 0; j < DP_; j++) {
        cb[j] = conn_b[a * DP_ + j];
        bo[j] = b_out[a * DP_ + j];
    }
    const float* cwa = cw + a * DP_ * DP_;

    float cur[DP_], vv[DP_], rr[DP_], sp[DP_], fr[DP_];
#pragma unroll
    for (int j = 0; j < DP_; j++) { cur[j] = 0.f; vv[j] = 0.f; rr[j] = 0.f; sp[j] = 0.f; fr[j] = 0.f; }

    for (int t = 0; t < T_; t++) {
        const float* xp = x3 + ((size_t)b * T_ + t) * OUT_ + a * DP_;
        float sn[DP_];
#pragma unroll
        for (int j = 0; j < DP_; j++) {
            float lat = cb[j];
#pragma unroll
            for (int k = 0; k < DP_; k++) lat += sp[k] * cwa[j * DP_ + k];
            float c  = cur[j] * CDECAY + xp[j] + bo[j] + lat;
            float v2 = vv[j] * (1.0f - sp[j]) + sp[j] * THR;
            float r2 = rr[j] + sp[j] * THS;
            float vd = v2 * v2 - v2 - r2 + c;
            float rd = THV * v2 - THU * r2;
            v2 += vd; r2 += rd;
            sn[j] = v2 > VTH ? 1.0f : 0.0f;
            cur[j] = c; vv[j] = v2; rr[j] = r2;
        }
#pragma unroll
        for (int j = 0; j < DP_; j++) { sp[j] = sn[j]; fr[j] += sn[j]; }
    }

    float raw = dec_b[a];
#pragma unroll
    for (int p = 0; p < DP_; p++) raw += (fr[p] * 0.125f) * dec_w[a * DP_ + p];
    out[idx] = tanhf(raw);
}

// ---------------- launch ----------------
extern "C" void kernel_launch(void* const* d_in, const int* in_sizes, int n_in,
                              void* d_out, int out_size) {
    const float* obs    = (const float*)d_in[0];
    const float* mean   = (const float*)d_in[1];
    const float* stdv   = (const float*)d_in[2];
    const float* w1     = (const float*)d_in[3];
    const float* b1     = (const float*)d_in[4];
    const float* w2     = (const float*)d_in[5];
    const float* b2     = (const float*)d_in[6];
    const float* w_out  = (const float*)d_in[7];
    const float* b_out  = (const float*)d_in[8];
    const float* conn_w = (const float*)d_in[9];
    const float* conn_b = (const float*)d_in[10];
    const float* dec_w  = (const float*)d_in[11];
    const float* dec_b  = (const float*)d_in[12];
    float* out = (float*)d_out;

    int8_t *spikes, *sa, *sb;
    float *x3, *w1t, *w2t, *wot;
    cudaGetSymbolAddress((void**)&spikes, g_spikes);
    cudaGetSymbolAddress((void**)&sa,  g_sa);
    cudaGetSymbolAddress((void**)&sb,  g_sb);
    cudaGetSymbolAddress((void**)&x3,  g_x3);
    cudaGetSymbolAddress((void**)&w1t, g_w1t);
    cudaGetSymbolAddress((void**)&w2t, g_w2t);
    cudaGetSymbolAddress((void**)&wot, g_wot);

    const int smemG = 2 * 32 * 128 * 4 + 2 * 32 * 128 * 4;   // 65536
    const int smemO = 2 * 32 * 128 * 4 + 2 * 32 * 160 * 4;   // 73728
    cudaFuncSetAttribute(gemm_f2<640, 1>,  cudaFuncAttributeMaxDynamicSharedMemorySize, smemG);
    cudaFuncSetAttribute(gemm_f2<1024, 1>, cudaFuncAttributeMaxDynamicSharedMemorySize, smemG);
    cudaFuncSetAttribute(gemm_f2_l3,       cudaFuncAttributeMaxDynamicSharedMemorySize, smemO);

    {
        dim3 tb(32, 8);
        transpose_w<<<dim3(32, 20), tb>>>(w1, w1t, H_, IN_, H_);
        transpose_w<<<dim3(32, 32), tb>>>(w2, w2t, H_, H_, H_);
        transpose_w<<<dim3(5, 32),  tb>>>(w_out, wot, OUT_, H_, OUT_);
    }
    encoder_kernel<<<(B_ * IN_ + 255) / 256, 256>>>(obs, mean, stdv);

    // L1: s1 = scan(spikes_all @ W1)   (M=32768, K=640, N=1024, fused scan)
    gemm_f2<640, 1><<<dim3(8, M_ / 128), 256, smemG>>>(
        spikes, w1t, b1, nullptr, sa, H_, H_, H_);

    // L2: s2 = scan(s1_all @ W2)       (M=32768, K=1024, N=1024, fused scan)
    gemm_f2<1024, 1><<<dim3(8, M_ / 128), 256, smemG>>>(
        sa, w2t, b2, nullptr, sb, H_, H_, H_);

    // L3: X3 = s2_all @ Wout           (M=32768, K=1024, N=160 exact)
    gemm_f2_l3<<<dim3(1, M_ / 128), 256, smemO>>>(sb, wot, x3);

    // output scan: lateral + neuron + fr + decode
    scan_out<<<(B_ * AD_ + 255) / 256, 256>>>(x3, b_out, conn_w, conn_b, dec_w, dec_b, out);
}

// round 16
// speedup vs baseline: 1.7468x; 1.2659x over previous
#include <cuda_runtime.h>
#include <cstdint>

// ---------------- problem constants ----------------
#define B_     4096
#define OBS_   64
#define EP_    10
#define IN_    640      // OBS*EP
#define H_     1024
#define AD_    16
#define DP_    10
#define OUT_   160      // AD*DP
#define T_     8
#define M_     (B_ * T_)   // 32768 batched rows, ordered m = b*8 + t

#define CDECAY 0.5f
#define VTH    0.5f
#define THV   (-0.172f)
#define THU    0.529f
#define THR    0.021f
#define THS    0.132f

// ---------------- device scratch ----------------
__device__ __align__(128) int8_t g_spikes[(size_t)M_ * (size_t)IN_];   // 21 MB, [b*8+t][i]
__device__ __align__(128) int8_t g_sa[(size_t)M_ * (size_t)H_];        // 33.5 MB
__device__ __align__(128) int8_t g_sb[(size_t)M_ * (size_t)H_];        // 33.5 MB
__device__ __align__(128) float g_x3[(size_t)M_ * (size_t)OUT_];       // 21 MB
__device__ __align__(128) float g_w1t[(size_t)IN_ * (size_t)H_];   // [640][1024]
__device__ __align__(128) float g_w2t[(size_t)H_ * (size_t)H_];    // [1024][1024]
__device__ __align__(128) float g_wot[(size_t)H_ * (size_t)OUT_];  // [1024][160]

// ---------------- helpers ----------------
__device__ __forceinline__ uint32_t smem_u32(const void* p) {
    uint32_t a;
    asm("{ .reg .u64 t; cvta.to.shared.u64 t, %1; cvt.u32.u64 %0, t; }" : "=r"(a) : "l"(p));
    return a;
}
__device__ __forceinline__ void cp_async16(uint32_t saddr, const void* g) {
    asm volatile("cp.async.cg.shared.global [%0], [%1], 16;" :: "r"(saddr), "l"(g));
}
#define CP_COMMIT() asm volatile("cp.async.commit_group;" ::: "memory")
#define CP_WAIT0()  asm volatile("cp.async.wait_group 0;" ::: "memory")

__device__ __forceinline__ void lds_v2u64(unsigned long long& a, unsigned long long& b, uint32_t addr) {
    asm volatile("ld.shared.v2.u64 {%0,%1}, [%2];" : "=l"(a), "=l"(b) : "r"(addr));
}
__device__ __forceinline__ void lds_f4(float4& v, uint32_t addr) {
    asm volatile("ld.shared.v4.f32 {%0,%1,%2,%3}, [%4];"
        : "=f"(v.x), "=f"(v.y), "=f"(v.z), "=f"(v.w) : "f"(v.x) , "r"(addr));
}
__device__ __forceinline__ void lds_f4b(float4& v, uint32_t addr) {
    asm volatile("ld.shared.v4.f32 {%0,%1,%2,%3}, [%4];"
        : "=f"(v.x), "=f"(v.y), "=f"(v.z), "=f"(v.w) : "r"(addr));
}
__device__ __forceinline__ float lds_f1(uint32_t addr) {
    float v;
    asm volatile("ld.shared.f32 %0, [%1];" : "=f"(v) : "r"(addr));
    return v;
}
__device__ __forceinline__ void sts32(uint32_t addr, uint32_t d) {
    asm volatile("st.shared.b32 [%0], %1;" :: "r"(addr), "r"(d));
}
__device__ __forceinline__ unsigned long long dup2(float x) {
    unsigned long long d;
    uint32_t u = __float_as_uint(x);
    asm("mov.b64 %0, {%1,%1};" : "=l"(d) : "r"(u));
    return d;
}
// packed fp32 pair FMA: per-lane IEEE RN fp32 fma (bitwise == scalar FFMA chain)
__device__ __forceinline__ void fma2(unsigned long long& d, unsigned long long a, unsigned long long b) {
    asm("fma.rn.f32x2 %0, %1, %2, %0;" : "+l"(d) : "l"(a), "l"(b));
}
__device__ __forceinline__ float f2lo(unsigned long long u) {
    return __int_as_float((int)(unsigned)(u & 0xffffffffull));
}
__device__ __forceinline__ float f2hi(unsigned long long u) {
    return __int_as_float((int)(unsigned)(u >> 32));
}

// warp k-activity mask: lane j tests k=j over the warp's 16 rows (broadcast LDS).
// Skipping k where all 16 rows are 0.0f is BITWISE exact (fma(0,w,acc)==acc;
// acc never -0 in an RN accumulation chain starting from +0).
__device__ __forceinline__ uint32_t warp_kmask(uint32_t ab_rowbase) {
    const uint32_t ak = ab_rowbase + (uint32_t)(threadIdx.x & 31) * 512u;
    unsigned long long t0, t1, t2, t3, t4, t5, t6, t7;
    lds_v2u64(t0, t1, ak);
    lds_v2u64(t2, t3, ak + 16u);
    lds_v2u64(t4, t5, ak + 32u);
    lds_v2u64(t6, t7, ak + 48u);
    unsigned long long o = (t0 | t1) | (t2 | t3) | ((t4 | t5) | (t6 | t7));
    return __ballot_sync(0xffffffffu, o != 0ull);
}

// ---------------- batched f32x2 GEMM (BN=128), sequential-k fp32 semantics ----------------
// X[m][n] = sum_{k ascending} A[m][k]*W[n][k], fp32 RN FMA chain per output.
// A: s8 spikes [M][KBASE], m = b*8+t. WT: fp32 [KBASE][WLD] k-major.
// CTA 128x128, BK=32, 256 threads; thread: 16 rows (2 batches x t0..7) x 4 cols.
// Warp-uniform sparsity skip: dense path identical to R15; sparse path ffs-ordered.
// MODE 0: plain store to X. MODE 1: fused hidden-neuron scan over t, write s8 spikes.
template<int KBASE, int MODE>
__global__ __launch_bounds__(256, 2) void gemm_f2(
    const int8_t* __restrict__ A, const float* __restrict__ WT,
    const float* __restrict__ bias,
    float* __restrict__ X, int8_t* __restrict__ S,
    int WLD, int XLD, int NTOT) {

    constexpr int KT = KBASE / 32;
    constexpr uint32_t ABUF = 32 * 128 * 4;
    constexpr uint32_t WBUF = 32 * 128 * 4;

    extern __shared__ char smraw[];
    const uint32_t ab0 = smem_u32(smraw);
    const uint32_t wb0 = ab0 + 2 * ABUF;

    const int tid  = threadIdx.x;
    const int trow = tid >> 5;     // 0..7   (16 rows each)
    const int tcol = tid & 31;     // 0..31  (4 cols each)
    const int bm0 = blockIdx.y * 128;
    const int bn0 = blockIdx.x * 128;

    const int arowi = tid & 127;
    const int khalf = tid >> 7;    // 0/1
    const int8_t* arow = A + (size_t)(bm0 + arowi) * KBASE + khalf * 16;

    uint4 arg;
    auto ldgA = [&](int t) { arg = *(const uint4*)(arow + t * 32); };
    auto cpW = [&](int t) {
        const float* src = WT + (size_t)(t * 32) * WLD + bn0;
        const uint32_t dst = wb0 + (uint32_t)(t & 1) * WBUF;
#pragma unroll
        for (int q = 0; q < 4; q++) {
            int ch = tid + q * 256;           // 0..1023
            int row = ch >> 5, c16 = ch & 31; // 32 rows x 32 16B-chunks
            cp_async16(dst + (uint32_t)(row * 128 + c16 * 4) * 4,
                       src + (size_t)row * WLD + c16 * 4);
        }
        CP_COMMIT();
    };
    auto stsA = [&](int t) {
        uint32_t base = ab0 + (uint32_t)(t & 1) * ABUF
                      + (uint32_t)(khalf * 16 * 128 + arowi) * 4u;
#pragma unroll
        for (int w = 0; w < 4; w++) {
            uint32_t x = ((const uint32_t*)&arg)[w];
#pragma unroll
            for (int b = 0; b < 4; b++)
                sts32(base + (uint32_t)((w * 4 + b) * 128) * 4u,
                      ((x >> (8 * b)) & 1u) * 0x3f800000u);
        }
    };

    // acc[p][c]: f32x2 over rows (2p, 2p+1), col c
    unsigned long long acc[8][4];
#pragma unroll
    for (int p = 0; p < 8; p++)
#pragma unroll
        for (int c = 0; c < 4; c++) acc[p][c] = 0ull;

    // prologue
    ldgA(0); cpW(0); stsA(0);

    for (int i = 0; i < KT; i++) {
        CP_WAIT0();
        __syncthreads();
        if (i + 1 < KT) { cpW(i + 1); ldgA(i + 1); }

        const uint32_t ab = ab0 + (uint32_t)(i & 1) * ABUF + (uint32_t)(trow * 16) * 4u;
        const uint32_t wb = wb0 + (uint32_t)(i & 1) * WBUF + (uint32_t)(tcol * 4) * 4u;

        auto body = [&](int k) {
            unsigned long long ap[8];
            const uint32_t ak = ab + (uint32_t)(k * 128) * 4u;
            lds_v2u64(ap[0], ap[1], ak);
            lds_v2u64(ap[2], ap[3], ak + 16u);
            lds_v2u64(ap[4], ap[5], ak + 32u);
            lds_v2u64(ap[6], ap[7], ak + 48u);
            float4 w4;
            lds_f4b(w4, wb + (uint32_t)(k * 128) * 4u);
            unsigned long long wd[4];
            wd[0] = dup2(w4.x); wd[1] = dup2(w4.y);
            wd[2] = dup2(w4.z); wd[3] = dup2(w4.w);
#pragma unroll
            for (int p = 0; p < 8; p++)
#pragma unroll
                for (int c = 0; c < 4; c++) fma2(acc[p][c], ap[p], wd[c]);
        };

        uint32_t mask = warp_kmask(ab);
        if (mask == 0xffffffffu) {
#pragma unroll
            for (int k = 0; k < 32; k++) body(k);
        } else {
            while (mask) {
                int k = __ffs(mask) - 1;   // ascending k order
                mask &= mask - 1;
                body(k);
            }
        }
        if (i + 1 < KT) stsA(i + 1);
    }

    if (MODE == 1) {
        // fused hidden-neuron scan: thread rows = 2 batch groups x t 0..7
        float bj[4];
#pragma unroll
        for (int c = 0; c < 4; c++) bj[c] = bias[bn0 + tcol * 4 + c];
        uint32_t srow[16];
#pragma unroll
        for (int i = 0; i < 16; i++) srow[i] = 0u;
#pragma unroll
        for (int c = 0; c < 4; c++) {
#pragma unroll
            for (int g = 0; g < 2; g++) {
                float cu = 0.0f, vv = 0.0f, rr = 0.0f, ss = 0.0f;
#pragma unroll
                for (int t = 0; t < T_; t++) {
                    unsigned long long a = acc[g * 4 + (t >> 1)][c];
                    float xv = (t & 1) ? f2hi(a) : f2lo(a);
                    cu = cu * CDECAY + xv + bj[c];
                    vv = vv * (1.0f - ss) + ss * THR;
                    rr = rr + ss * THS;
                    float vd = vv * vv - vv - rr + cu;
                    float rd = THV * vv - THU * rr;
                    vv += vd; rr += rd;
                    ss = vv > VTH ? 1.0f : 0.0f;
                    srow[g * 8 + t] |= (ss != 0.0f ? 1u : 0u) << (8 * c);
                }
            }
        }
#pragma unroll
        for (int i = 0; i < 16; i++) {
            size_t row = (size_t)(bm0 + trow * 16 + i);
            *(uint32_t*)&S[row * H_ + bn0 + tcol * 4] = srow[i];
        }
    } else {
#pragma unroll
        for (int i = 0; i < 16; i++) {
            int row = bm0 + trow * 16 + i;
            int col = bn0 + tcol * 4;
            if (col < NTOT) {
                const int p = i >> 1, e = i & 1;
                float4 v;
                v.x = e ? f2hi(acc[p][0]) : f2lo(acc[p][0]);
                v.y = e ? f2hi(acc[p][1]) : f2lo(acc[p][1]);
                v.z = e ? f2hi(acc[p][2]) : f2lo(acc[p][2]);
                v.w = e ? f2hi(acc[p][3]) : f2lo(acc[p][3]);
                *(float4*)&X[(size_t)row * XLD + col] = v;
            }
        }
    }
}

// ---------------- L3 GEMM: BN=160 exact, with sparsity skip ----------------
// CTA 128 x 160, grid (1, M/128). Thread: 16 rows x 5 cols, cols = tcol + c*32.
__global__ __launch_bounds__(256, 2) void gemm_f2_l3(
    const int8_t* __restrict__ A, const float* __restrict__ WT,
    float* __restrict__ X) {

    constexpr int KB = 1024, KT = KB / 32;
    constexpr uint32_t ABUF = 32 * 128 * 4;
    constexpr uint32_t WBUF = 32 * 160 * 4;

    extern __shared__ char smraw[];
    const uint32_t ab0 = smem_u32(smraw);
    const uint32_t wb0 = ab0 + 2 * ABUF;

    const int tid  = threadIdx.x;
    const int trow = tid >> 5;     // 0..7
    const int tcol = tid & 31;     // 0..31
    const int bm0 = blockIdx.y * 128;

    const int arowi = tid & 127;
    const int khalf = tid >> 7;
    const int8_t* arow = A + (size_t)(bm0 + arowi) * KB + khalf * 16;

    uint4 arg;
    auto ldgA = [&](int t) { arg = *(const uint4*)(arow + t * 32); };
    auto cpW = [&](int t) {
        const float* src = WT + (size_t)(t * 32) * OUT_;
        const uint32_t dst = wb0 + (uint32_t)(t & 1) * WBUF;
#pragma unroll
        for (int q = 0; q < 5; q++) {
            int ch = tid + q * 256;          // 0..1279
            int row = ch / 40, c16 = ch % 40; // 32 rows x 40 16B-chunks
            cp_async16(dst + (uint32_t)(row * 160 + c16 * 4) * 4,
                       src + (size_t)row * OUT_ + c16 * 4);
        }
        CP_COMMIT();
    };
    auto stsA = [&](int t) {
        uint32_t base = ab0 + (uint32_t)(t & 1) * ABUF
                      + (uint32_t)(khalf * 16 * 128 + arowi) * 4u;
#pragma unroll
        for (int w = 0; w < 4; w++) {
            uint32_t x = ((const uint32_t*)&arg)[w];
#pragma unroll
            for (int b = 0; b < 4; b++)
                sts32(base + (uint32_t)((w * 4 + b) * 128) * 4u,
                      ((x >> (8 * b)) & 1u) * 0x3f800000u);
        }
    };

    unsigned long long acc[8][5];
#pragma unroll
    for (int p = 0; p < 8; p++)
#pragma unroll
        for (int c = 0; c < 5; c++) acc[p][c] = 0ull;

    ldgA(0); cpW(0); stsA(0);

    for (int i = 0; i < KT; i++) {
        CP_WAIT0();
        __syncthreads();
        if (i + 1 < KT) { cpW(i + 1); ldgA(i + 1); }

        const uint32_t ab = ab0 + (uint32_t)(i & 1) * ABUF + (uint32_t)(trow * 16) * 4u;
        const uint32_t wb = wb0 + (uint32_t)(i & 1) * WBUF + (uint32_t)tcol * 4u;

        auto body = [&](int k) {
            unsigned long long ap[8];
            const uint32_t ak = ab + (uint32_t)(k * 128) * 4u;
            lds_v2u64(ap[0], ap[1], ak);
            lds_v2u64(ap[2], ap[3], ak + 16u);
            lds_v2u64(ap[4], ap[5], ak + 32u);
            lds_v2u64(ap[6], ap[7], ak + 48u);
            const uint32_t wk = wb + (uint32_t)(k * 160) * 4u;
            unsigned long long wd[5];
#pragma unroll
            for (int c = 0; c < 5; c++) wd[c] = dup2(lds_f1(wk + (uint32_t)(c * 32) * 4u));
#pragma unroll
            for (int p = 0; p < 8; p++)
#pragma unroll
                for (int c = 0; c < 5; c++) fma2(acc[p][c], ap[p], wd[c]);
        };

        uint32_t mask = warp_kmask(ab);
        if (mask == 0xffffffffu) {
#pragma unroll
            for (int k = 0; k < 32; k++) body(k);
        } else {
            while (mask) {
                int k = __ffs(mask) - 1;
                mask &= mask - 1;
                body(k);
            }
        }
        if (i + 1 < KT) stsA(i + 1);
    }

    // epilogue: scalar stores, cols tcol + c*32
#pragma unroll
    for (int i = 0; i < 16; i++) {
        int row = bm0 + trow * 16 + i;
        const int p = i >> 1, e = i & 1;
        float* xr = X + (size_t)row * OUT_ + tcol;
#pragma unroll
        for (int c = 0; c < 5; c++)
            xr[c * 32] = e ? f2hi(acc[p][c]) : f2lo(acc[p][c]);
    }
}

// ---------------- weight transpose: w[N][K] -> wt[K][NP] ----------------
__global__ void transpose_w(const float* __restrict__ w, float* __restrict__ wt,
                            int N, int K, int NP) {
    __shared__ float t[32][33];
    int tx = threadIdx.x, ty = threadIdx.y;  // 32 x 8
    int bx = blockIdx.x, by = blockIdx.y;
#pragma unroll
    for (int j = 0; j < 4; j++) {
        int n = bx * 32 + ty + j * 8;
        int k = by * 32 + tx;
        t[ty + j * 8][tx] = (n < N) ? w[(size_t)n * K + k] : 0.0f;
    }
    __syncthreads();
#pragma unroll
    for (int j = 0; j < 4; j++) {
        int k = by * 32 + ty + j * 8;
        int n = bx * 32 + tx;
        if (n < NP) wt[(size_t)k * NP + n] = t[tx][ty + j * 8];
    }
}

// ---------------- encoder (writes spikes in m = b*8+t order) ----------------
__global__ void encoder_kernel(const float* __restrict__ obs,
                               const float* __restrict__ mean,
                               const float* __restrict__ stdv) {
    int idx = blockIdx.x * blockDim.x + threadIdx.x;
    if (idx >= B_ * IN_) return;
    int b = idx / IN_;
    int i = idx - b * IN_;
    int o = i / EP_;
    float d  = obs[b * OBS_ + o] - mean[i];
    float sd = stdv[i];
    float a  = expf(-0.5f * d * d / (sd * sd));
    float volt = 0.0f;
    int8_t* sp = g_spikes + (size_t)b * T_ * IN_ + i;
#pragma unroll
    for (int t = 0; t < T_; t++) {
        volt += a;
        float s = volt > 1.0f ? 1.0f : 0.0f;
        volt -= s;
        sp[(size_t)t * IN_] = (int8_t)s;
    }
}

// ---------------- output-layer scan: lateral conv + neuron + fr + decode ----------------
__global__ __launch_bounds__(256) void scan_out(
    const float* __restrict__ x3, const float* __restrict__ b_out,
    const float* __restrict__ conn_w, const float* __restrict__ conn_b,
    const float* __restrict__ dec_w, const float* __restrict__ dec_b,
    float* __restrict__ out) {
    __shared__ float cw[AD_ * DP_ * DP_];   // 1600
    for (int i = threadIdx.x; i < AD_ * DP_ * DP_; i += blockDim.x) cw[i] = conn_w[i];
    __syncthreads();

    int idx = blockIdx.x * blockDim.x + threadIdx.x;   // (b, a)
    if (idx >= B_ * AD_) return;
    int b = idx >> 4;
    int a = idx & 15;

    float cb[DP_], bo[DP_];
#pragma unroll
    for (int j = 0; j < DP_; j++) {
        cb[j] = conn_b[a * DP_ + j];
        bo[j] = b_out[a * DP_ + j];
    }
    const float* cwa = cw + a * DP_ * DP_;

    float cur[DP_], vv[DP_], rr[DP_], sp[DP_], fr[DP_];
#pragma unroll
    for (int j = 0; j < DP_; j++) { cur[j] = 0.f; vv[j] = 0.f; rr[j] = 0.f; sp[j] = 0.f; fr[j] = 0.f; }

    for (int t = 0; t < T_; t++) {
        const float* xp = x3 + ((size_t)b * T_ + t) * OUT_ + a * DP_;
        float sn[DP_];
#pragma unroll
        for (int j = 0; j < DP_; j++) {
            float lat = cb[j];
#pragma unroll
            for (int k = 0; k < DP_; k++) lat += sp[k] * cwa[j * DP_ + k];
            float c  = cur[j] * CDECAY + xp[j] + bo[j] + lat;
            float v2 = vv[j] * (1.0f - sp[j]) + sp[j] * THR;
            float r2 = rr[j] + sp[j] * THS;
            float vd = v2 * v2 - v2 - r2 + c;
            float rd = THV * v2 - THU * r2;
            v2 += vd; r2 += rd;
            sn[j] = v2 > VTH ? 1.0f : 0.0f;
            cur[j] = c; vv[j] = v2; rr[j] = r2;
        }
#pragma unroll
        for (int j = 0; j < DP_; j++) { sp[j] = sn[j]; fr[j] += sn[j]; }
    }

    float raw = dec_b[a];
#pragma unroll
    for (int p = 0; p < DP_; p++) raw += (fr[p] * 0.125f) * dec_w[a * DP_ + p];
    out[idx] = tanhf(raw);
}

// ---------------- launch ----------------
extern "C" void kernel_launch(void* const* d_in, const int* in_sizes, int n_in,
                              void* d_out, int out_size) {
    const float* obs    = (const float*)d_in[0];
    const float* mean   = (const float*)d_in[1];
    const float* stdv   = (const float*)d_in[2];
    const float* w1     = (const float*)d_in[3];
    const float* b1     = (const float*)d_in[4];
    const float* w2     = (const float*)d_in[5];
    const float* b2     = (const float*)d_in[6];
    const float* w_out  = (const float*)d_in[7];
    const float* b_out  = (const float*)d_in[8];
    const float* conn_w = (const float*)d_in[9];
    const float* conn_b = (const float*)d_in[10];
    const float* dec_w  = (const float*)d_in[11];
    const float* dec_b  = (const float*)d_in[12];
    float* out = (float*)d_out;

    int8_t *spikes, *sa, *sb;
    float *x3, *w1t, *w2t, *wot;
    cudaGetSymbolAddress((void**)&spikes, g_spikes);
    cudaGetSymbolAddress((void**)&sa,  g_sa);
    cudaGetSymbolAddress((void**)&sb,  g_sb);
    cudaGetSymbolAddress((void**)&x3,  g_x3);
    cudaGetSymbolAddress((void**)&w1t, g_w1t);
    cudaGetSymbolAddress((void**)&w2t, g_w2t);
    cudaGetSymbolAddress((void**)&wot, g_wot);

    const int smemG = 2 * 32 * 128 * 4 + 2 * 32 * 128 * 4;   // 65536
    const int smemO = 2 * 32 * 128 * 4 + 2 * 32 * 160 * 4;   // 73728
    cudaFuncSetAttribute(gemm_f2<640, 1>,  cudaFuncAttributeMaxDynamicSharedMemorySize, smemG);
    cudaFuncSetAttribute(gemm_f2<1024, 1>, cudaFuncAttributeMaxDynamicSharedMemorySize, smemG);
    cudaFuncSetAttribute(gemm_f2_l3,       cudaFuncAttributeMaxDynamicSharedMemorySize, smemO);

    {
        dim3 tb(32, 8);
        transpose_w<<<dim3(32, 20), tb>>>(w1, w1t, H_, IN_, H_);
        transpose_w<<<dim3(32, 32), tb>>>(w2, w2t, H_, H_, H_);
        transpose_w<<<dim3(5, 32),  tb>>>(w_out, wot, OUT_, H_, OUT_);
    }
    encoder_kernel<<<(B_ * IN_ + 255) / 256, 256>>>(obs, mean, stdv);

    // L1: s1 = scan(spikes_all @ W1)   (M=32768, K=640, N=1024, fused scan)
    gemm_f2<640, 1><<<dim3(8, M_ / 128), 256, smemG>>>(
        spikes, w1t, b1, nullptr, sa, H_, H_, H_);

    // L2: s2 = scan(s1_all @ W2)       (M=32768, K=1024, N=1024, fused scan)
    gemm_f2<1024, 1><<<dim3(8, M_ / 128), 256, smemG>>>(
        sa, w2t, b2, nullptr, sb, H_, H_, H_);

    // L3: X3 = s2_all @ Wout           (M=32768, K=1024, N=160 exact)
    gemm_f2_l3<<<dim3(1, M_ / 128), 256, smemO>>>(sb, wot, x3);

    // output scan: lateral + neuron + fr + decode
    scan_out<<<(B_ * AD_ + 255) / 256, 256>>>(x3, b_out, conn_w, conn_b, dec_w, dec_b, out);
}

// round 17
// speedup vs baseline: 2.0550x; 1.1764x over previous
#include <cuda_runtime.h>
#include <cstdint>

// ---------------- problem constants ----------------
#define B_     4096
#define OBS_   64
#define EP_    10
#define IN_    640      // OBS*EP
#define H_     1024
#define AD_    16
#define DP_    10
#define OUT_   160      // AD*DP
#define T_     8
#define M_     (B_ * T_)   // 32768 batched rows, ordered m = b*8 + t

#define CDECAY 0.5f
#define VTH    0.5f
#define THV   (-0.172f)
#define THU    0.529f
#define THR    0.021f
#define THS    0.132f

// ---------------- device scratch ----------------
__device__ __align__(128) int8_t g_spikes[(size_t)M_ * (size_t)IN_];   // 21 MB, [b*8+t][i]
__device__ __align__(128) int8_t g_sa[(size_t)M_ * (size_t)H_];        // 33.5 MB
__device__ __align__(128) int8_t g_sb[(size_t)M_ * (size_t)H_];        // 33.5 MB
__device__ __align__(128) float g_x3[(size_t)M_ * (size_t)OUT_];       // 21 MB
__device__ __align__(128) float g_w1t[(size_t)IN_ * (size_t)H_];   // [640][1024]
__device__ __align__(128) float g_w2t[(size_t)H_ * (size_t)H_];    // [1024][1024]
__device__ __align__(128) float g_wot[(size_t)H_ * (size_t)OUT_];  // [1024][160]

// ---------------- helpers ----------------
__device__ __forceinline__ uint32_t smem_u32(const void* p) {
    uint32_t a;
    asm("{ .reg .u64 t; cvta.to.shared.u64 t, %1; cvt.u32.u64 %0, t; }" : "=r"(a) : "l"(p));
    return a;
}
__device__ __forceinline__ void cp_async16(uint32_t saddr, const void* g) {
    asm volatile("cp.async.cg.shared.global [%0], [%1], 16;" :: "r"(saddr), "l"(g));
}
#define CP_COMMIT() asm volatile("cp.async.commit_group;" ::: "memory")
#define CP_WAIT0()  asm volatile("cp.async.wait_group 0;" ::: "memory")

__device__ __forceinline__ void lds_v2u64(unsigned long long& a, unsigned long long& b, uint32_t addr) {
    asm volatile("ld.shared.v2.u64 {%0,%1}, [%2];" : "=l"(a), "=l"(b) : "r"(addr));
}
__device__ __forceinline__ void lds_f4b(float4& v, uint32_t addr) {
    asm volatile("ld.shared.v4.f32 {%0,%1,%2,%3}, [%4];"
        : "=f"(v.x), "=f"(v.y), "=f"(v.z), "=f"(v.w) : "r"(addr));
}
__device__ __forceinline__ float lds_f1(uint32_t addr) {
    float v;
    asm volatile("ld.shared.f32 %0, [%1];" : "=f"(v) : "r"(addr));
    return v;
}
__device__ __forceinline__ void sts32(uint32_t addr, uint32_t d) {
    asm volatile("st.shared.b32 [%0], %1;" :: "r"(addr), "r"(d));
}
__device__ __forceinline__ unsigned long long dup2(float x) {
    unsigned long long d;
    uint32_t u = __float_as_uint(x);
    asm("mov.b64 %0, {%1,%1};" : "=l"(d) : "r"(u));
    return d;
}
// packed fp32 pair FMA: per-lane IEEE RN fp32 fma (bitwise == scalar FFMA chain)
__device__ __forceinline__ void fma2(unsigned long long& d, unsigned long long a, unsigned long long b) {
    asm("fma.rn.f32x2 %0, %1, %2, %0;" : "+l"(d) : "l"(a), "l"(b));
}
__device__ __forceinline__ float f2lo(unsigned long long u) {
    return __int_as_float((int)(unsigned)(u & 0xffffffffull));
}
__device__ __forceinline__ float f2hi(unsigned long long u) {
    return __int_as_float((int)(unsigned)(u >> 32));
}

// warp k-activity masks, split by 8-row batch group. Lane j tests k=j over the
// warp's 16 broadcast rows. Skipping k where a group's 8 rows are all 0.0f is
// BITWISE exact per that group's outputs (fma(0,w,acc)==acc; acc never -0 in an
// RN accumulation chain starting from +0).
__device__ __forceinline__ void warp_kmask2(uint32_t ab_rowbase,
                                            uint32_t& m0, uint32_t& m1) {
    const uint32_t ak = ab_rowbase + (uint32_t)(threadIdx.x & 31) * 512u;
    unsigned long long t0, t1, t2, t3, t4, t5, t6, t7;
    lds_v2u64(t0, t1, ak);
    lds_v2u64(t2, t3, ak + 16u);
    lds_v2u64(t4, t5, ak + 32u);
    lds_v2u64(t6, t7, ak + 48u);
    unsigned long long g0 = (t0 | t1) | (t2 | t3);
    unsigned long long g1 = (t4 | t5) | (t6 | t7);
    m0 = __ballot_sync(0xffffffffu, g0 != 0ull);
    m1 = __ballot_sync(0xffffffffu, g1 != 0ull);
}

// ---------------- batched f32x2 GEMM (BN=128), sequential-k fp32 semantics ----------------
// X[m][n] = sum_{k ascending} A[m][k]*W[n][k], fp32 RN FMA chain per output.
// A: s8 spikes [M][KBASE], m = b*8+t. WT: fp32 [KBASE][WLD] k-major.
// CTA 128x128, BK=32, 256 threads; thread: 16 rows (2 batches x t0..7) x 4 cols.
// Sparsity: per-batch-group masks; dense fallback when popc sum >= 48.
// MODE 0: plain store to X. MODE 1: fused hidden-neuron scan over t, write s8 spikes.
template<int KBASE, int MODE>
__global__ __launch_bounds__(256, 2) void gemm_f2(
    const int8_t* __restrict__ A, const float* __restrict__ WT,
    const float* __restrict__ bias,
    float* __restrict__ X, int8_t* __restrict__ S,
    int WLD, int XLD, int NTOT) {

    constexpr int KT = KBASE / 32;
    constexpr uint32_t ABUF = 32 * 128 * 4;
    constexpr uint32_t WBUF = 32 * 128 * 4;

    extern __shared__ char smraw[];
    const uint32_t ab0 = smem_u32(smraw);
    const uint32_t wb0 = ab0 + 2 * ABUF;

    const int tid  = threadIdx.x;
    const int trow = tid >> 5;     // 0..7   (16 rows each)
    const int tcol = tid & 31;     // 0..31  (4 cols each)
    const int bm0 = blockIdx.y * 128;
    const int bn0 = blockIdx.x * 128;

    const int arowi = tid & 127;
    const int khalf = tid >> 7;    // 0/1
    const int8_t* arow = A + (size_t)(bm0 + arowi) * KBASE + khalf * 16;

    uint4 arg;
    auto ldgA = [&](int t) { arg = *(const uint4*)(arow + t * 32); };
    auto cpW = [&](int t) {
        const float* src = WT + (size_t)(t * 32) * WLD + bn0;
        const uint32_t dst = wb0 + (uint32_t)(t & 1) * WBUF;
#pragma unroll
        for (int q = 0; q < 4; q++) {
            int ch = tid + q * 256;           // 0..1023
            int row = ch >> 5, c16 = ch & 31; // 32 rows x 32 16B-chunks
            cp_async16(dst + (uint32_t)(row * 128 + c16 * 4) * 4,
                       src + (size_t)row * WLD + c16 * 4);
        }
        CP_COMMIT();
    };
    auto stsA = [&](int t) {
        uint32_t base = ab0 + (uint32_t)(t & 1) * ABUF
                      + (uint32_t)(khalf * 16 * 128 + arowi) * 4u;
#pragma unroll
        for (int w = 0; w < 4; w++) {
            uint32_t x = ((const uint32_t*)&arg)[w];
#pragma unroll
            for (int b = 0; b < 4; b++)
                sts32(base + (uint32_t)((w * 4 + b) * 128) * 4u,
                      ((x >> (8 * b)) & 1u) * 0x3f800000u);
        }
    };

    // acc[p][c]: f32x2 over rows (2p, 2p+1), col c; pairs 0-3 = group0, 4-7 = group1
    unsigned long long acc[8][4];
#pragma unroll
    for (int p = 0; p < 8; p++)
#pragma unroll
        for (int c = 0; c < 4; c++) acc[p][c] = 0ull;

    // prologue
    ldgA(0); cpW(0); stsA(0);

    for (int i = 0; i < KT; i++) {
        CP_WAIT0();
        __syncthreads();
        if (i + 1 < KT) { cpW(i + 1); ldgA(i + 1); }

        const uint32_t ab = ab0 + (uint32_t)(i & 1) * ABUF + (uint32_t)(trow * 16) * 4u;
        const uint32_t wb = wb0 + (uint32_t)(i & 1) * WBUF + (uint32_t)(tcol * 4) * 4u;

        auto body = [&](int k) {
            unsigned long long ap[8];
            const uint32_t ak = ab + (uint32_t)(k * 128) * 4u;
            lds_v2u64(ap[0], ap[1], ak);
            lds_v2u64(ap[2], ap[3], ak + 16u);
            lds_v2u64(ap[4], ap[5], ak + 32u);
            lds_v2u64(ap[6], ap[7], ak + 48u);
            float4 w4;
            lds_f4b(w4, wb + (uint32_t)(k * 128) * 4u);
            unsigned long long wd[4];
            wd[0] = dup2(w4.x); wd[1] = dup2(w4.y);
            wd[2] = dup2(w4.z); wd[3] = dup2(w4.w);
#pragma unroll
            for (int p = 0; p < 8; p++)
#pragma unroll
                for (int c = 0; c < 4; c++) fma2(acc[p][c], ap[p], wd[c]);
        };
        auto body_g = [&](int k, int g) {
            unsigned long long ap[4];
            const uint32_t ak = ab + (uint32_t)(k * 128) * 4u + (uint32_t)(g * 32);
            lds_v2u64(ap[0], ap[1], ak);
            lds_v2u64(ap[2], ap[3], ak + 16u);
            float4 w4;
            lds_f4b(w4, wb + (uint32_t)(k * 128) * 4u);
            unsigned long long wd[4];
            wd[0] = dup2(w4.x); wd[1] = dup2(w4.y);
            wd[2] = dup2(w4.z); wd[3] = dup2(w4.w);
#pragma unroll
            for (int p = 0; p < 4; p++)
#pragma unroll
                for (int c = 0; c < 4; c++) fma2(acc[g * 4 + p][c], ap[p], wd[c]);
        };

        uint32_t m0, m1;
        warp_kmask2(ab, m0, m1);
        if (__popc(m0) + __popc(m1) >= 48) {
#pragma unroll
            for (int k = 0; k < 32; k++) body(k);
        } else {
            uint32_t m = m0;
            while (m) { int k = __ffs(m) - 1; m &= m - 1; body_g(k, 0); }
            m = m1;
            while (m) { int k = __ffs(m) - 1; m &= m - 1; body_g(k, 1); }
        }
        if (i + 1 < KT) stsA(i + 1);
    }

    if (MODE == 1) {
        // fused hidden-neuron scan: thread rows = 2 batch groups x t 0..7
        float bj[4];
#pragma unroll
        for (int c = 0; c < 4; c++) bj[c] = bias[bn0 + tcol * 4 + c];
        uint32_t srow[16];
#pragma unroll
        for (int i = 0; i < 16; i++) srow[i] = 0u;
#pragma unroll
        for (int c = 0; c < 4; c++) {
#pragma unroll
            for (int g = 0; g < 2; g++) {
                float cu = 0.0f, vv = 0.0f, rr = 0.0f, ss = 0.0f;
#pragma unroll
                for (int t = 0; t < T_; t++) {
                    unsigned long long a = acc[g * 4 + (t >> 1)][c];
                    float xv = (t & 1) ? f2hi(a) : f2lo(a);
                    cu = cu * CDECAY + xv + bj[c];
                    vv = vv * (1.0f - ss) + ss * THR;
                    rr = rr + ss * THS;
                    float vd = vv * vv - vv - rr + cu;
                    float rd = THV * vv - THU * rr;
                    vv += vd; rr += rd;
                    ss = vv > VTH ? 1.0f : 0.0f;
                    srow[g * 8 + t] |= (ss != 0.0f ? 1u : 0u) << (8 * c);
                }
            }
        }
#pragma unroll
        for (int i = 0; i < 16; i++) {
            size_t row = (size_t)(bm0 + trow * 16 + i);
            *(uint32_t*)&S[row * H_ + bn0 + tcol * 4] = srow[i];
        }
    } else {
#pragma unroll
        for (int i = 0; i < 16; i++) {
            int row = bm0 + trow * 16 + i;
            int col = bn0 + tcol * 4;
            if (col < NTOT) {
                const int p = i >> 1, e = i & 1;
                float4 v;
                v.x = e ? f2hi(acc[p][0]) : f2lo(acc[p][0]);
                v.y = e ? f2hi(acc[p][1]) : f2lo(acc[p][1]);
                v.z = e ? f2hi(acc[p][2]) : f2lo(acc[p][2]);
                v.w = e ? f2hi(acc[p][3]) : f2lo(acc[p][3]);
                *(float4*)&X[(size_t)row * XLD + col] = v;
            }
        }
    }
}

// ---------------- L3 GEMM: BN=160 exact, group-split sparsity ----------------
// CTA 128 x 160, grid (1, M/128). Thread: 16 rows x 5 cols, cols = tcol + c*32.
__global__ __launch_bounds__(256, 2) void gemm_f2_l3(
    const int8_t* __restrict__ A, const float* __restrict__ WT,
    float* __restrict__ X) {

    constexpr int KB = 1024, KT = KB / 32;
    constexpr uint32_t ABUF = 32 * 128 * 4;
    constexpr uint32_t WBUF = 32 * 160 * 4;

    extern __shared__ char smraw[];
    const uint32_t ab0 = smem_u32(smraw);
    const uint32_t wb0 = ab0 + 2 * ABUF;

    const int tid  = threadIdx.x;
    const int trow = tid >> 5;     // 0..7
    const int tcol = tid & 31;     // 0..31
    const int bm0 = blockIdx.y * 128;

    const int arowi = tid & 127;
    const int khalf = tid >> 7;
    const int8_t* arow = A + (size_t)(bm0 + arowi) * KB + khalf * 16;

    uint4 arg;
    auto ldgA = [&](int t) { arg = *(const uint4*)(arow + t * 32); };
    auto cpW = [&](int t) {
        const float* src = WT + (size_t)(t * 32) * OUT_;
        const uint32_t dst = wb0 + (uint32_t)(t & 1) * WBUF;
#pragma unroll
        for (int q = 0; q < 5; q++) {
            int ch = tid + q * 256;          // 0..1279
            int row = ch / 40, c16 = ch % 40; // 32 rows x 40 16B-chunks
            cp_async16(dst + (uint32_t)(row * 160 + c16 * 4) * 4,
                       src + (size_t)row * OUT_ + c16 * 4);
        }
        CP_COMMIT();
    };
    auto stsA = [&](int t) {
        uint32_t base = ab0 + (uint32_t)(t & 1) * ABUF
                      + (uint32_t)(khalf * 16 * 128 + arowi) * 4u;
#pragma unroll
        for (int w = 0; w < 4; w++) {
            uint32_t x = ((const uint32_t*)&arg)[w];
#pragma unroll
            for (int b = 0; b < 4; b++)
                sts32(base + (uint32_t)((w * 4 + b) * 128) * 4u,
                      ((x >> (8 * b)) & 1u) * 0x3f800000u);
        }
    };

    unsigned long long acc[8][5];
#pragma unroll
    for (int p = 0; p < 8; p++)
#pragma unroll
        for (int c = 0; c < 5; c++) acc[p][c] = 0ull;

    ldgA(0); cpW(0); stsA(0);

    for (int i = 0; i < KT; i++) {
        CP_WAIT0();
        __syncthreads();
        if (i + 1 < KT) { cpW(i + 1); ldgA(i + 1); }

        const uint32_t ab = ab0 + (uint32_t)(i & 1) * ABUF + (uint32_t)(trow * 16) * 4u;
        const uint32_t wb = wb0 + (uint32_t)(i & 1) * WBUF + (uint32_t)tcol * 4u;

        auto body = [&](int k) {
            unsigned long long ap[8];
            const uint32_t ak = ab + (uint32_t)(k * 128) * 4u;
            lds_v2u64(ap[0], ap[1], ak);
            lds_v2u64(ap[2], ap[3], ak + 16u);
            lds_v2u64(ap[4], ap[5], ak + 32u);
            lds_v2u64(ap[6], ap[7], ak + 48u);
            const uint32_t wk = wb + (uint32_t)(k * 160) * 4u;
            unsigned long long wd[5];
#pragma unroll
            for (int c = 0; c < 5; c++) wd[c] = dup2(lds_f1(wk + (uint32_t)(c * 32) * 4u));
#pragma unroll
            for (int p = 0; p < 8; p++)
#pragma unroll
                for (int c = 0; c < 5; c++) fma2(acc[p][c], ap[p], wd[c]);
        };
        auto body_g = [&](int k, int g) {
            unsigned long long ap[4];
            const uint32_t ak = ab + (uint32_t)(k * 128) * 4u + (uint32_t)(g * 32);
            lds_v2u64(ap[0], ap[1], ak);
            lds_v2u64(ap[2], ap[3], ak + 16u);
            const uint32_t wk = wb + (uint32_t)(k * 160) * 4u;
            unsigned long long wd[5];
#pragma unroll
            for (int c = 0; c < 5; c++) wd[c] = dup2(lds_f1(wk + (uint32_t)(c * 32) * 4u));
#pragma unroll
            for (int p = 0; p < 4; p++)
#pragma unroll
                for (int c = 0; c < 5; c++) fma2(acc[g * 4 + p][c], ap[p], wd[c]);
        };

        uint32_t m0, m1;
        warp_kmask2(ab, m0, m1);
        if (__popc(m0) + __popc(m1) >= 48) {
#pragma unroll
            for (int k = 0; k < 32; k++) body(k);
        } else {
            uint32_t m = m0;
            while (m) { int k = __ffs(m) - 1; m &= m - 1; body_g(k, 0); }
            m = m1;
            while (m) { int k = __ffs(m) - 1; m &= m - 1; body_g(k, 1); }
        }
        if (i + 1 < KT) stsA(i + 1);
    }

    // epilogue: scalar stores, cols tcol + c*32
#pragma unroll
    for (int i = 0; i < 16; i++) {
        int row = bm0 + trow * 16 + i;
        const int p = i >> 1, e = i & 1;
        float* xr = X + (size_t)row * OUT_ + tcol;
#pragma unroll
        for (int c = 0; c < 5; c++)
            xr[c * 32] = e ? f2hi(acc[p][c]) : f2lo(acc[p][c]);
    }
}

// ---------------- weight transpose: w[N][K] -> wt[K][NP] ----------------
__global__ void transpose_w(const float* __restrict__ w, float* __restrict__ wt,
                            int N, int K, int NP) {
    __shared__ float t[32][33];
    int tx = threadIdx.x, ty = threadIdx.y;  // 32 x 8
    int bx = blockIdx.x, by = blockIdx.y;
#pragma unroll
    for (int j = 0; j < 4; j++) {
        int n = bx * 32 + ty + j * 8;
        int k = by * 32 + tx;
        t[ty + j * 8][tx] = (n < N) ? w[(size_t)n * K + k] : 0.0f;
    }
    __syncthreads();
#pragma unroll
    for (int j = 0; j < 4; j++) {
        int k = by * 32 + ty + j * 8;
        int n = bx * 32 + tx;
        if (n < NP) wt[(size_t)k * NP + n] = t[tx][ty + j * 8];
    }
}

// ---------------- encoder (writes spikes in m = b*8+t order) ----------------
__global__ void encoder_kernel(const float* __restrict__ obs,
                               const float* __restrict__ mean,
                               const float* __restrict__ stdv) {
    int idx = blockIdx.x * blockDim.x + threadIdx.x;
    if (idx >= B_ * IN_) return;
    int b = idx / IN_;
    int i = idx - b * IN_;
    int o = i / EP_;
    float d  = obs[b * OBS_ + o] - mean[i];
    float sd = stdv[i];
    float a  = expf(-0.5f * d * d / (sd * sd));
    float volt = 0.0f;
    int8_t* sp = g_spikes + (size_t)b * T_ * IN_ + i;
#pragma unroll
    for (int t = 0; t < T_; t++) {
        volt += a;
        float s = volt > 1.0f ? 1.0f : 0.0f;
        volt -= s;
        sp[(size_t)t * IN_] = (int8_t)s;
    }
}

// ---------------- output-layer scan: lateral conv + neuron + fr + decode ----------------
__global__ __launch_bounds__(256) void scan_out(
    const float* __restrict__ x3, const float* __restrict__ b_out,
    const float* __restrict__ conn_w, const float* __restrict__ conn_b,
    const float* __restrict__ dec_w, const float* __restrict__ dec_b,
    float* __restrict__ out) {
    __shared__ float cw[AD_ * DP_ * DP_];   // 1600
    for (int i = threadIdx.x; i < AD_ * DP_ * DP_; i += blockDim.x) cw[i] = conn_w[i];
    __syncthreads();

    int idx = blockIdx.x * blockDim.x + threadIdx.x;   // (b, a)
    if (idx >= B_ * AD_) return;
    int b = idx >> 4;
    int a = idx & 15;

    float cb[DP_], bo[DP_];
#pragma unroll
    for (int j = 0; j < DP_; j++) {
        cb[j] = conn_b[a * DP_ + j];
        bo[j] = b_out[a * DP_ + j];
    }
    const float* cwa = cw + a * DP_ * DP_;

    float cur[DP_], vv[DP_], rr[DP_], sp[DP_], fr[DP_];
#pragma unroll
    for (int j = 0; j < DP_; j++) { cur[j] = 0.f; vv[j] = 0.f; rr[j] = 0.f; sp[j] = 0.f; fr[j] = 0.f; }

    for (int t = 0; t < T_; t++) {
        const float* xp = x3 + ((size_t)b * T_ + t) * OUT_ + a * DP_;
        float sn[DP_];
#pragma unroll
        for (int j = 0; j < DP_; j++) {
            float lat = cb[j];
#pragma unroll
            for (int k = 0; k < DP_; k++) lat += sp[k] * cwa[j * DP_ + k];
            float c  = cur[j] * CDECAY + xp[j] + bo[j] + lat;
            float v2 = vv[j] * (1.0f - sp[j]) + sp[j] * THR;
            float r2 = rr[j] + sp[j] * THS;
            float vd = v2 * v2 - v2 - r2 + c;
            float rd = THV * v2 - THU * r2;
            v2 += vd; r2 += rd;
            sn[j] = v2 > VTH ? 1.0f : 0.0f;
            cur[j] = c; vv[j] = v2; rr[j] = r2;
        }
#pragma unroll
        for (int j = 0; j < DP_; j++) { sp[j] = sn[j]; fr[j] += sn[j]; }
    }

    float raw = dec_b[a];
#pragma unroll
    for (int p = 0; p < DP_; p++) raw += (fr[p] * 0.125f) * dec_w[a * DP_ + p];
    out[idx] = tanhf(raw);
}

// ---------------- launch ----------------
extern "C" void kernel_launch(void* const* d_in, const int* in_sizes, int n_in,
                              void* d_out, int out_size) {
    const float* obs    = (const float*)d_in[0];
    const float* mean   = (const float*)d_in[1];
    const float* stdv   = (const float*)d_in[2];
    const float* w1     = (const float*)d_in[3];
    const float* b1     = (const float*)d_in[4];
    const float* w2     = (const float*)d_in[5];
    const float* b2     = (const float*)d_in[6];
    const float* w_out  = (const float*)d_in[7];
    const float* b_out  = (const float*)d_in[8];
    const float* conn_w = (const float*)d_in[9];
    const float* conn_b = (const float*)d_in[10];
    const float* dec_w  = (const float*)d_in[11];
    const float* dec_b  = (const float*)d_in[12];
    float* out = (float*)d_out;

    int8_t *spikes, *sa, *sb;
    float *x3, *w1t, *w2t, *wot;
    cudaGetSymbolAddress((void**)&spikes, g_spikes);
    cudaGetSymbolAddress((void**)&sa,  g_sa);
    cudaGetSymbolAddress((void**)&sb,  g_sb);
    cudaGetSymbolAddress((void**)&x3,  g_x3);
    cudaGetSymbolAddress((void**)&w1t, g_w1t);
    cudaGetSymbolAddress((void**)&w2t, g_w2t);
    cudaGetSymbolAddress((void**)&wot, g_wot);

    const int smemG = 2 * 32 * 128 * 4 + 2 * 32 * 128 * 4;   // 65536
    const int smemO = 2 * 32 * 128 * 4 + 2 * 32 * 160 * 4;   // 73728
    cudaFuncSetAttribute(gemm_f2<640, 1>,  cudaFuncAttributeMaxDynamicSharedMemorySize, smemG);
    cudaFuncSetAttribute(gemm_f2<1024, 1>, cudaFuncAttributeMaxDynamicSharedMemorySize, smemG);
    cudaFuncSetAttribute(gemm_f2_l3,       cudaFuncAttributeMaxDynamicSharedMemorySize, smemO);

    {
        dim3 tb(32, 8);
        transpose_w<<<dim3(32, 20), tb>>>(w1, w1t, H_, IN_, H_);
        transpose_w<<<dim3(32, 32), tb>>>(w2, w2t, H_, H_, H_);
        transpose_w<<<dim3(5, 32),  tb>>>(w_out, wot, OUT_, H_, OUT_);
    }
    encoder_kernel<<<(B_ * IN_ + 255) / 256, 256>>>(obs, mean, stdv);

    // L1: s1 = scan(spikes_all @ W1)   (M=32768, K=640, N=1024, fused scan)
    gemm_f2<640, 1><<<dim3(8, M_ / 128), 256, smemG>>>(
        spikes, w1t, b1, nullptr, sa, H_, H_, H_);

    // L2: s2 = scan(s1_all @ W2)       (M=32768, K=1024, N=1024, fused scan)
    gemm_f2<1024, 1><<<dim3(8, M_ / 128), 256, smemG>>>(
        sa, w2t, b2, nullptr, sb, H_, H_, H_);

    // L3: X3 = s2_all @ Wout           (M=32768, K=1024, N=160 exact)
    gemm_f2_l3<<<dim3(1, M_ / 128), 256, smemO>>>(sb, wot, x3);

    // output scan: lateral + neuron + fr + decode
    scan_out<<<(B_ * AD_ + 255) / 256, 256>>>(x3, b_out, conn_w, conn_b, dec_w, dec_b, out);
}